// round 8
// baseline (speedup 1.0000x reference)
#include <cuda_runtime.h>
#include <cuda_fp16.h>
#include <math.h>
#include <stdint.h>
#include <string.h>

// ---------------------------------------------------------------------------
// Problem constants
// ---------------------------------------------------------------------------
#define BB 16
#define LL 4096
#define HH 512
#define PP 256
#define MM (BB * LL)          // 65536 rows
#define KK 512                // GEMM K
#define CH 128                // scan chunk length
#define NCHUNK (LL / CH)      // 32
#define LN_EPS 1e-6f

// GEMM tiling
#define BM 128
#define BN 128
#define BK 32
#define NIT (KK / BK)         // 16
#define BKP 40                // A smem k-stride (halves)
#define BNP 136               // B smem n-stride (halves)
// 3-stage smem layout
#define SA_BYTES 10240        // 128*40*2
#define SB_BYTES 8704         // 32*136*2
#define STG_BYTES (SA_BYTES + SB_BYTES)   // 18944
#define NSTG 3
#define SM_BYTES (NSTG * STG_BYTES)       // 56832 >= 33792 (C tile reuse)
#define CT_STRIDE 66          // half2 per row (132 halves)

// ---------------------------------------------------------------------------
// Scratch (static __device__)
// Interleaved complex: col 2p = re, col 2p+1 = im.
// ---------------------------------------------------------------------------
__device__ __half g_Bu[(size_t)MM * KK];
__device__ __half g_XS[(size_t)MM * KK];
__device__ __half g_ysh[(size_t)MM * HH];
__device__ __half g_W1[KK * HH];
__device__ __half g_W2[KK * HH];
__device__ float g_lbar[2 * PP];
__device__ float g_a32[2 * PP];    // lbar^32
__device__ float g_aC[2 * PP];     // lbar^128
__device__ float g_coef[2 * PP];
__device__ float g_carry[BB * NCHUNK * 2 * PP];

// ---------------------------------------------------------------------------
// PTX helpers
// ---------------------------------------------------------------------------
__device__ __forceinline__ uint32_t s2u(const void* p) {
    return (uint32_t)__cvta_generic_to_shared(p);
}
__device__ __forceinline__ void ldsm4(uint32_t* r, uint32_t a) {
    asm volatile("ldmatrix.sync.aligned.m8n8.x4.shared.b16 {%0,%1,%2,%3},[%4];\n"
                 : "=r"(r[0]), "=r"(r[1]), "=r"(r[2]), "=r"(r[3]) : "r"(a));
}
__device__ __forceinline__ void ldsm4t(uint32_t* r, uint32_t a) {
    asm volatile("ldmatrix.sync.aligned.m8n8.x4.trans.shared.b16 {%0,%1,%2,%3},[%4];\n"
                 : "=r"(r[0]), "=r"(r[1]), "=r"(r[2]), "=r"(r[3]) : "r"(a));
}
__device__ __forceinline__ void mma16816(float* d, const uint32_t* a, uint32_t b0, uint32_t b1) {
    asm volatile("mma.sync.aligned.m16n8k16.row.col.f32.f16.f16.f32 "
                 "{%0,%1,%2,%3},{%4,%5,%6,%7},{%8,%9},{%0,%1,%2,%3};\n"
                 : "+f"(d[0]), "+f"(d[1]), "+f"(d[2]), "+f"(d[3])
                 : "r"(a[0]), "r"(a[1]), "r"(a[2]), "r"(a[3]), "r"(b0), "r"(b1));
}
__device__ __forceinline__ void cp16(uint32_t dst, const void* src) {
    asm volatile("cp.async.cg.shared.global [%0], [%1], 16;" :: "r"(dst), "l"(src));
}
__device__ __forceinline__ void cp_commit() {
    asm volatile("cp.async.commit_group;" ::: "memory");
}
__device__ __forceinline__ void cp_wait1() {
    asm volatile("cp.async.wait_group 1;" ::: "memory");
}
__device__ __forceinline__ void cp_wait0() {
    asm volatile("cp.async.wait_group 0;" ::: "memory");
}

// ---------------------------------------------------------------------------
// Setup: per-p scalars
// ---------------------------------------------------------------------------
__global__ void k_setup_small(const float* __restrict__ log_lambda_re,
                              const float* __restrict__ lambda_im,
                              const float* __restrict__ log_step) {
    int p = threadIdx.x;
    if (p >= PP) return;
    float lam_re = -expf(log_lambda_re[p]);
    float lam_im = lambda_im[p];
    float st = expf(log_step[p]);
    float ar = lam_re * st, ai = lam_im * st;
    float e = expf(ar);
    float lbr = e * cosf(ai);
    float lbi = e * sinf(ai);
    g_lbar[p] = lbr; g_lbar[PP + p] = lbi;
    float nr = lbr - 1.0f, ni = lbi;
    float d2 = lam_re * lam_re + lam_im * lam_im;
    g_coef[p]      = (nr * lam_re + ni * lam_im) / d2;
    g_coef[PP + p] = (ni * lam_re - nr * lam_im) / d2;
    float sr = lbr, si = lbi;
    #pragma unroll
    for (int i = 0; i < 5; i++) {          // ^32
        float r2 = sr * sr - si * si;
        float i2 = 2.0f * sr * si;
        sr = r2; si = i2;
    }
    g_a32[p] = sr; g_a32[PP + p] = si;
    #pragma unroll
    for (int i = 0; i < 2; i++) {          // ^128
        float r2 = sr * sr - si * si;
        float i2 = 2.0f * sr * si;
        sr = r2; si = i2;
    }
    g_aC[p] = sr; g_aC[PP + p] = si;
}

// ---------------------------------------------------------------------------
// Setup: folded weights [k][n], fp16, interleaved complex columns
// ---------------------------------------------------------------------------
__global__ void k_setup_W(const float* __restrict__ B_re, const float* __restrict__ B_im,
                          const float* __restrict__ C_re, const float* __restrict__ C_im) {
    int idx = blockIdx.x * blockDim.x + threadIdx.x;
    if (idx >= PP * HH) return;
    int p = idx / HH;
    int h = idx % HH;
    float cr = g_coef[p], ci = g_coef[PP + p];
    float br = B_re[p * HH + h], bi = B_im[p * HH + h];
    float w1r = cr * br - ci * bi;
    float w1i = cr * bi + ci * br;
    g_W1[h * KK + 2 * p]     = __float2half_rn(w1r);
    g_W1[h * KK + 2 * p + 1] = __float2half_rn(w1i);
    g_W2[(2 * p) * HH + h]     = __float2half_rn( 2.0f * C_re[h * PP + p]);
    g_W2[(2 * p + 1) * HH + h] = __float2half_rn(-2.0f * C_im[h * PP + p]);
}

// ---------------------------------------------------------------------------
// 3-stage pipelined fp16 GEMM, 2 CTAs/SM.
// CONV: A fp32 via LDG->regs->deferred STS.  !CONV: A fp16 via cp.async.
// FUSE: after store, compute scan-chunk carry from the C tile (GEMM1 only).
// ---------------------------------------------------------------------------
template <bool CONV, bool FUSE>
__global__ __launch_bounds__(256, 2) void k_gemm_f16(
    const float* __restrict__ Af,
    const __half* __restrict__ Ah,
    const __half* __restrict__ W,
    __half* __restrict__ C)
{
    __shared__ __align__(16) char sm[SM_BYTES];
    __shared__ float2 s_part[4][64];

    uint32_t smb = s2u(sm);
    int tid = threadIdx.x;
    int bx = blockIdx.x, by = blockIdx.y;
    int lane = tid & 31, wid = tid >> 5;
    int wm = (wid & 1) * 64;
    int wn = (wid >> 1) * 32;

    int a_r = lane & 15;
    int a_c = (lane >> 4) * 8;
    int b_r = (lane & 7) + ((lane >> 3) & 1) * 8;
    int b_c = (lane >> 4) * 8;

    float acc[4][4][4];
    #pragma unroll
    for (int i = 0; i < 4; i++)
        #pragma unroll
        for (int j = 0; j < 4; j++)
            #pragma unroll
            for (int c = 0; c < 4; c++) acc[i][j][c] = 0.0f;

    int af_row = tid >> 3, af_col = (tid & 7) * 4;
    float4 areg[4];

    auto sA = [&](int st) { return smb + st * STG_BYTES; };
    auto sB = [&](int st) { return smb + st * STG_BYTES + SA_BYTES; };

    auto cpB = [&](int it, int st) {
        uint32_t base = sB(st);
        #pragma unroll
        for (int i = 0; i < 2; i++) {
            int cidx = tid + 256 * i;
            int row = cidx >> 4;
            int c16 = cidx & 15;
            cp16(base + row * 272 + c16 * 16,
                 W + (size_t)(it * BK + row) * 512 + bx * BN + c16 * 8);
        }
    };
    auto cpA = [&](int it, int st) {
        uint32_t base = sA(st);
        #pragma unroll
        for (int i = 0; i < 2; i++) {
            int cidx = tid + 256 * i;
            int row = cidx >> 2;
            int c16 = cidx & 3;
            cp16(base + row * 80 + c16 * 16,
                 Ah + (size_t)(by * BM + row) * 512 + it * BK + c16 * 8);
        }
    };
    auto ldgA = [&](int it) {
        #pragma unroll
        for (int r = 0; r < 4; r++)
            areg[r] = *reinterpret_cast<const float4*>(
                Af + (size_t)(by * BM + af_row + r * 32) * 512 + it * BK + af_col);
    };
    auto stsA = [&](int st) {
        uint32_t base = sA(st);
        #pragma unroll
        for (int r = 0; r < 4; r++) {
            float4 v = areg[r];
            __half2 h0 = __floats2half2_rn(v.x, v.y);
            __half2 h1 = __floats2half2_rn(v.z, v.w);
            uint32_t u0, u1;
            memcpy(&u0, &h0, 4); memcpy(&u1, &h1, 4);
            asm volatile("st.shared.v2.b32 [%0], {%1, %2};"
                :: "r"(base + ((af_row + r * 32) * BKP + af_col) * 2), "r"(u0), "r"(u1)
                : "memory");
        }
    };

    // prologue: stages 0 and 1
    cpB(0, 0);
    if (CONV) { ldgA(0); stsA(0); } else cpA(0, 0);
    cp_commit();
    cpB(1, 1);
    if (CONV) { ldgA(1); stsA(1); } else cpA(1, 1);
    cp_commit();

    for (int it = 0; it < NIT; it++) {
        int st = it % NSTG;
        if (it == NIT - 1) cp_wait0(); else cp_wait1();
        __syncthreads();
        bool pf = (it + 2 < NIT);
        if (pf) {
            int st2 = (it + 2) % NSTG;
            cpB(it + 2, st2);
            if (CONV) ldgA(it + 2);
            else cpA(it + 2, st2);
            cp_commit();
        }

        uint32_t a_base = sA(st), b_base = sB(st);
        #pragma unroll
        for (int ks = 0; ks < BK; ks += 16) {
            uint32_t bf[2][4];
            #pragma unroll
            for (int j2 = 0; j2 < 2; j2++)
                ldsm4t(bf[j2], b_base + ((ks + b_r) * BNP + wn + j2 * 16 + b_c) * 2);
            #pragma unroll
            for (int i = 0; i < 4; i++) {
                uint32_t a[4];
                ldsm4(a, a_base + ((wm + i * 16 + a_r) * BKP + ks + a_c) * 2);
                #pragma unroll
                for (int j = 0; j < 4; j++)
                    mma16816(acc[i][j], a, bf[j >> 1][(j & 1) * 2], bf[j >> 1][(j & 1) * 2 + 1]);
            }
        }
        if (pf && CONV) stsA((it + 2) % NSTG);
    }

    if (FUSE) __syncthreads();
    __half2* Ct = reinterpret_cast<__half2*>(sm);

    // --- store C (fp16), optionally also to smem tile for fused scan ---
    #pragma unroll
    for (int i = 0; i < 4; i++) {
        int rl0 = wm + i * 16 + (lane >> 2);
        int r0 = by * BM + rl0;
        int cl0 = wn + (lane & 3) * 2;
        int c0 = bx * BN + cl0;
        #pragma unroll
        for (int j = 0; j < 4; j++) {
            __half2 v0 = __floats2half2_rn(acc[i][j][0], acc[i][j][1]);
            __half2 v1 = __floats2half2_rn(acc[i][j][2], acc[i][j][3]);
            *reinterpret_cast<__half2*>(&C[(size_t)r0 * 512 + c0 + j * 8]) = v0;
            *reinterpret_cast<__half2*>(&C[(size_t)(r0 + 8) * 512 + c0 + j * 8]) = v1;
            if (FUSE) {
                Ct[rl0 * CT_STRIDE + ((cl0 + j * 8) >> 1)] = v0;
                Ct[(rl0 + 8) * CT_STRIDE + ((cl0 + j * 8) >> 1)] = v1;
            }
        }
    }

    if (FUSE) {
        __syncthreads();
        int seg = tid >> 6;
        int pl = tid & 63;
        int pg = bx * 64 + pl;
        float ar = g_lbar[pg], ai = g_lbar[PP + pg];
        float sr = 0.0f, si = 0.0f;
        int t0 = seg * 32;
        #pragma unroll 4
        for (int t = t0; t < t0 + 32; t++) {
            float2 v = __half22float2(Ct[t * CT_STRIDE + pl]);
            float nr = fmaf(ar, sr, fmaf(-ai, si, v.x));
            float ni = fmaf(ar, si, fmaf(ai, sr, v.y));
            sr = nr; si = ni;
        }
        s_part[seg][pl] = make_float2(sr, si);
        __syncthreads();
        if (tid < 64) {
            int pg2 = bx * 64 + tid;
            float a32r = g_a32[pg2], a32i = g_a32[PP + pg2];
            float2 c = s_part[0][tid];
            #pragma unroll
            for (int k = 1; k < 4; k++) {
                float2 pk = s_part[k][tid];
                float cr = a32r * c.x - a32i * c.y + pk.x;
                float ci = a32r * c.y + a32i * c.x + pk.y;
                c.x = cr; c.y = ci;
            }
            size_t o = ((size_t)by * PP + pg2) * 2;
            g_carry[o] = c.x;
            g_carry[o + 1] = c.y;
        }
    }
}

// ---------------------------------------------------------------------------
// Scan apply with inline prefix: each (b,j) block loads carries 0..j-1 with
// full MLP (predicated batch load), combines in registers, then recomputes
// the chunk recurrence and writes xs.
// ---------------------------------------------------------------------------
__global__ __launch_bounds__(256) void k_scan_apply() {
    int blk = blockIdx.x;
    int b = blk / NCHUNK;
    int j = blk % NCHUNK;
    int p = threadIdx.x;
    float a128r = g_aC[p], a128i = g_aC[PP + p];

    // batch-load carries (independent addresses -> one round trip)
    const float2* cr2 = reinterpret_cast<const float2*>(g_carry);
    float2 cb[NCHUNK];
    #pragma unroll
    for (int i = 0; i < NCHUNK; i++)
        if (i < j) cb[i] = cr2[(size_t)(b * NCHUNK + i) * PP + p];

    float sr = 0.0f, si = 0.0f;
    #pragma unroll
    for (int i = 0; i < NCHUNK; i++) {
        if (i < j) {
            float nr = fmaf(a128r, sr, fmaf(-a128i, si, cb[i].x));
            float ni = fmaf(a128r, si, fmaf(a128i, sr, cb[i].y));
            sr = nr; si = ni;
        }
    }

    float ar = g_lbar[p], ai = g_lbar[PP + p];
    const __half2* bu = reinterpret_cast<const __half2*>(g_Bu);
    __half2* xs = reinterpret_cast<__half2*>(g_XS);
    size_t base = ((size_t)b * LL + (size_t)j * CH) * PP + p;
    #pragma unroll 4
    for (int t = 0; t < CH; t++) {
        float2 v = __half22float2(bu[base + (size_t)t * PP]);
        float nr = fmaf(ar, sr, fmaf(-ai, si, v.x));
        float ni = fmaf(ar, si, fmaf(ai, sr, v.y));
        sr = nr; si = ni;
        xs[base + (size_t)t * PP] = __floats2half2_rn(sr, si);
    }
}

// ---------------------------------------------------------------------------
// Epilogue: y = gelu_tanh(ys + x*D); z = x + y; LayerNorm over H
// ---------------------------------------------------------------------------
__global__ __launch_bounds__(256) void k_epilogue(const float* __restrict__ x,
                                                  const float* __restrict__ D,
                                                  const float* __restrict__ ln_scale,
                                                  const float* __restrict__ ln_bias,
                                                  float* __restrict__ out) {
    int row = blockIdx.x;
    int tid = threadIdx.x;
    const __half2* ysr = reinterpret_cast<const __half2*>(g_ysh + (size_t)row * HH);
    const float2* xr = reinterpret_cast<const float2*>(x + (size_t)row * HH);
    const float2* D2 = reinterpret_cast<const float2*>(D);
    float zv[2];
    float sum = 0.0f, sum2 = 0.0f;
    {
        float2 ys2 = __half22float2(ysr[tid]);
        float2 xv = xr[tid];
        float2 dv = D2[tid];
        float yy[2] = {ys2.x + xv.x * dv.x, ys2.y + xv.y * dv.y};
        float xsv[2] = {xv.x, xv.y};
        #pragma unroll
        for (int e = 0; e < 2; e++) {
            float y = yy[e];
            float y3 = y * y * y;
            float u = 0.7978845608028654f * (y + 0.044715f * y3);
            float g = 0.5f * y * (1.0f + tanhf(u));
            float z = xsv[e] + g;
            zv[e] = z;
            sum += z; sum2 += z * z;
        }
    }
    __shared__ float s1[8], s2[8], stats[2];
    #pragma unroll
    for (int off = 16; off > 0; off >>= 1) {
        sum  += __shfl_down_sync(0xFFFFFFFFu, sum, off);
        sum2 += __shfl_down_sync(0xFFFFFFFFu, sum2, off);
    }
    int lane = tid & 31, wid = tid >> 5;
    if (lane == 0) { s1[wid] = sum; s2[wid] = sum2; }
    __syncthreads();
    if (tid == 0) {
        float a = 0.0f, bsum = 0.0f;
        #pragma unroll
        for (int i = 0; i < 8; i++) { a += s1[i]; bsum += s2[i]; }
        float mean = a * (1.0f / HH);
        float var = bsum * (1.0f / HH) - mean * mean;
        stats[0] = mean;
        stats[1] = rsqrtf(var + LN_EPS);
    }
    __syncthreads();
    float mean = stats[0], rstd = stats[1];
    const float2* sc2 = reinterpret_cast<const float2*>(ln_scale);
    const float2* bi2 = reinterpret_cast<const float2*>(ln_bias);
    float2 sc = sc2[tid], bi = bi2[tid];
    float2 o;
    o.x = (zv[0] - mean) * rstd * sc.x + bi.x;
    o.y = (zv[1] - mean) * rstd * sc.y + bi.y;
    reinterpret_cast<float2*>(out + (size_t)row * HH)[tid] = o;
}

// ---------------------------------------------------------------------------
// Launch
// ---------------------------------------------------------------------------
extern "C" void kernel_launch(void* const* d_in, const int* in_sizes, int n_in,
                              void* d_out, int out_size) {
    const float* x             = (const float*)d_in[0];
    const float* log_lambda_re = (const float*)d_in[1];
    const float* lambda_im     = (const float*)d_in[2];
    const float* B_re          = (const float*)d_in[3];
    const float* B_im          = (const float*)d_in[4];
    const float* C_re          = (const float*)d_in[5];
    const float* C_im          = (const float*)d_in[6];
    const float* D             = (const float*)d_in[7];
    const float* log_step      = (const float*)d_in[8];
    const float* ln_scale      = (const float*)d_in[9];
    const float* ln_bias       = (const float*)d_in[10];
    float* out = (float*)d_out;

    k_setup_small<<<1, 256>>>(log_lambda_re, lambda_im, log_step);
    k_setup_W<<<(PP * HH + 255) / 256, 256>>>(B_re, B_im, C_re, C_im);

    __half *gBu, *gXS, *gYS, *gW1, *gW2;
    cudaGetSymbolAddress((void**)&gBu, g_Bu);
    cudaGetSymbolAddress((void**)&gXS, g_XS);
    cudaGetSymbolAddress((void**)&gYS, g_ysh);
    cudaGetSymbolAddress((void**)&gW1, g_W1);
    cudaGetSymbolAddress((void**)&gW2, g_W2);

    dim3 grid(HH / BN, MM / BM);   // (4, 512)

    // GEMM1: Bu = x @ W1 (fp32 A converted in-kernel) + fused chunk-carry
    k_gemm_f16<true, true><<<grid, 256>>>(x, nullptr, gW1, gBu);

    // scan apply (inline prefix from carries)
    k_scan_apply<<<BB * NCHUNK, 256>>>();

    // GEMM2: ys = xs @ W2 (fp16 A via cp.async)
    k_gemm_f16<false, false><<<grid, 256>>>(nullptr, gXS, gW2, gYS);

    // epilogue
    k_epilogue<<<MM, 256>>>(x, D, ln_scale, ln_bias, out);
}

// round 9
// speedup vs baseline: 1.1037x; 1.1037x over previous
#include <cuda_runtime.h>
#include <cuda_fp16.h>
#include <math.h>
#include <stdint.h>
#include <string.h>

// ---------------------------------------------------------------------------
// Problem constants
// ---------------------------------------------------------------------------
#define BB 16
#define LL 4096
#define HH 512
#define PP 256
#define MM (BB * LL)          // 65536 rows
#define KK 512                // GEMM K
#define CH 128                // scan chunk length
#define NCHUNK (LL / CH)      // 32
#define LN_EPS 1e-6f

// GEMM tiling
#define BM 128
#define BN 128
#define BK 32
#define NIT (KK / BK)         // 16
#define BKP 40                // A smem k-stride (halves)
#define BNP 136               // B smem n-stride (halves)
// 3-stage smem layout
#define SA_BYTES 10240        // 128*40*2
#define SB_BYTES 8704         // 32*136*2
#define STG_BYTES (SA_BYTES + SB_BYTES)   // 18944
#define NSTG 3
#define SM_BYTES (NSTG * STG_BYTES)       // 56832 >= 33792 (C tile reuse)
#define CT_STRIDE 66          // half2 per row (132 halves)

// ---------------------------------------------------------------------------
// Scratch (static __device__)
// Interleaved complex: col 2p = re, col 2p+1 = im.
// ---------------------------------------------------------------------------
__device__ __half g_Bu[(size_t)MM * KK];
__device__ __half g_XS[(size_t)MM * KK];
__device__ __half g_ysh[(size_t)MM * HH];
__device__ __half g_W1[KK * HH];
__device__ __half g_W2[KK * HH];
__device__ float g_lbar[2 * PP];
__device__ float g_a32[2 * PP];    // lbar^32
__device__ float g_aC[2 * PP];     // lbar^128
__device__ float g_coef[2 * PP];
__device__ float g_carry[BB * NCHUNK * 2 * PP];
__device__ float g_prefix[BB * NCHUNK * 2 * PP];

// ---------------------------------------------------------------------------
// PTX helpers
// ---------------------------------------------------------------------------
__device__ __forceinline__ uint32_t s2u(const void* p) {
    return (uint32_t)__cvta_generic_to_shared(p);
}
__device__ __forceinline__ void ldsm4(uint32_t* r, uint32_t a) {
    asm volatile("ldmatrix.sync.aligned.m8n8.x4.shared.b16 {%0,%1,%2,%3},[%4];\n"
                 : "=r"(r[0]), "=r"(r[1]), "=r"(r[2]), "=r"(r[3]) : "r"(a));
}
__device__ __forceinline__ void ldsm4t(uint32_t* r, uint32_t a) {
    asm volatile("ldmatrix.sync.aligned.m8n8.x4.trans.shared.b16 {%0,%1,%2,%3},[%4];\n"
                 : "=r"(r[0]), "=r"(r[1]), "=r"(r[2]), "=r"(r[3]) : "r"(a));
}
__device__ __forceinline__ void mma16816(float* d, const uint32_t* a, uint32_t b0, uint32_t b1) {
    asm volatile("mma.sync.aligned.m16n8k16.row.col.f32.f16.f16.f32 "
                 "{%0,%1,%2,%3},{%4,%5,%6,%7},{%8,%9},{%0,%1,%2,%3};\n"
                 : "+f"(d[0]), "+f"(d[1]), "+f"(d[2]), "+f"(d[3])
                 : "r"(a[0]), "r"(a[1]), "r"(a[2]), "r"(a[3]), "r"(b0), "r"(b1));
}
__device__ __forceinline__ void cp16(uint32_t dst, const void* src) {
    asm volatile("cp.async.cg.shared.global [%0], [%1], 16;" :: "r"(dst), "l"(src));
}
__device__ __forceinline__ void cp_commit() {
    asm volatile("cp.async.commit_group;" ::: "memory");
}
__device__ __forceinline__ void cp_wait1() {
    asm volatile("cp.async.wait_group 1;" ::: "memory");
}
__device__ __forceinline__ void cp_wait0() {
    asm volatile("cp.async.wait_group 0;" ::: "memory");
}

// ---------------------------------------------------------------------------
// Setup: per-p scalars
// ---------------------------------------------------------------------------
__global__ void k_setup_small(const float* __restrict__ log_lambda_re,
                              const float* __restrict__ lambda_im,
                              const float* __restrict__ log_step) {
    int p = threadIdx.x;
    if (p >= PP) return;
    float lam_re = -expf(log_lambda_re[p]);
    float lam_im = lambda_im[p];
    float st = expf(log_step[p]);
    float ar = lam_re * st, ai = lam_im * st;
    float e = expf(ar);
    float lbr = e * cosf(ai);
    float lbi = e * sinf(ai);
    g_lbar[p] = lbr; g_lbar[PP + p] = lbi;
    float nr = lbr - 1.0f, ni = lbi;
    float d2 = lam_re * lam_re + lam_im * lam_im;
    g_coef[p]      = (nr * lam_re + ni * lam_im) / d2;
    g_coef[PP + p] = (ni * lam_re - nr * lam_im) / d2;
    float sr = lbr, si = lbi;
    #pragma unroll
    for (int i = 0; i < 5; i++) {          // ^32
        float r2 = sr * sr - si * si;
        float i2 = 2.0f * sr * si;
        sr = r2; si = i2;
    }
    g_a32[p] = sr; g_a32[PP + p] = si;
    #pragma unroll
    for (int i = 0; i < 2; i++) {          // ^128
        float r2 = sr * sr - si * si;
        float i2 = 2.0f * sr * si;
        sr = r2; si = i2;
    }
    g_aC[p] = sr; g_aC[PP + p] = si;
}

// ---------------------------------------------------------------------------
// Setup: folded weights [k][n], fp16, interleaved complex columns
// ---------------------------------------------------------------------------
__global__ void k_setup_W(const float* __restrict__ B_re, const float* __restrict__ B_im,
                          const float* __restrict__ C_re, const float* __restrict__ C_im) {
    int idx = blockIdx.x * blockDim.x + threadIdx.x;
    if (idx >= PP * HH) return;
    int p = idx / HH;
    int h = idx % HH;
    float cr = g_coef[p], ci = g_coef[PP + p];
    float br = B_re[p * HH + h], bi = B_im[p * HH + h];
    float w1r = cr * br - ci * bi;
    float w1i = cr * bi + ci * br;
    g_W1[h * KK + 2 * p]     = __float2half_rn(w1r);
    g_W1[h * KK + 2 * p + 1] = __float2half_rn(w1i);
    g_W2[(2 * p) * HH + h]     = __float2half_rn( 2.0f * C_re[h * PP + p]);
    g_W2[(2 * p + 1) * HH + h] = __float2half_rn(-2.0f * C_im[h * PP + p]);
}

// ---------------------------------------------------------------------------
// 3-stage pipelined fp16 GEMM, 2 CTAs/SM.
// CONV: A fp32 via LDG->regs->deferred STS.  !CONV: A fp16 via cp.async.
// FUSE: after store, compute scan-chunk carry from the C tile (GEMM1 only).
// ---------------------------------------------------------------------------
template <bool CONV, bool FUSE>
__global__ __launch_bounds__(256, 2) void k_gemm_f16(
    const float* __restrict__ Af,
    const __half* __restrict__ Ah,
    const __half* __restrict__ W,
    __half* __restrict__ C)
{
    __shared__ __align__(16) char sm[SM_BYTES];
    __shared__ float2 s_part[4][64];

    uint32_t smb = s2u(sm);
    int tid = threadIdx.x;
    int bx = blockIdx.x, by = blockIdx.y;
    int lane = tid & 31, wid = tid >> 5;
    int wm = (wid & 1) * 64;
    int wn = (wid >> 1) * 32;

    int a_r = lane & 15;
    int a_c = (lane >> 4) * 8;
    int b_r = (lane & 7) + ((lane >> 3) & 1) * 8;
    int b_c = (lane >> 4) * 8;

    float acc[4][4][4];
    #pragma unroll
    for (int i = 0; i < 4; i++)
        #pragma unroll
        for (int j = 0; j < 4; j++)
            #pragma unroll
            for (int c = 0; c < 4; c++) acc[i][j][c] = 0.0f;

    int af_row = tid >> 3, af_col = (tid & 7) * 4;
    float4 areg[4];

    auto sA = [&](int st) { return smb + st * STG_BYTES; };
    auto sB = [&](int st) { return smb + st * STG_BYTES + SA_BYTES; };

    auto cpB = [&](int it, int st) {
        uint32_t base = sB(st);
        #pragma unroll
        for (int i = 0; i < 2; i++) {
            int cidx = tid + 256 * i;
            int row = cidx >> 4;
            int c16 = cidx & 15;
            cp16(base + row * 272 + c16 * 16,
                 W + (size_t)(it * BK + row) * 512 + bx * BN + c16 * 8);
        }
    };
    auto cpA = [&](int it, int st) {
        uint32_t base = sA(st);
        #pragma unroll
        for (int i = 0; i < 2; i++) {
            int cidx = tid + 256 * i;
            int row = cidx >> 2;
            int c16 = cidx & 3;
            cp16(base + row * 80 + c16 * 16,
                 Ah + (size_t)(by * BM + row) * 512 + it * BK + c16 * 8);
        }
    };
    auto ldgA = [&](int it) {
        #pragma unroll
        for (int r = 0; r < 4; r++)
            areg[r] = *reinterpret_cast<const float4*>(
                Af + (size_t)(by * BM + af_row + r * 32) * 512 + it * BK + af_col);
    };
    auto stsA = [&](int st) {
        uint32_t base = sA(st);
        #pragma unroll
        for (int r = 0; r < 4; r++) {
            float4 v = areg[r];
            __half2 h0 = __floats2half2_rn(v.x, v.y);
            __half2 h1 = __floats2half2_rn(v.z, v.w);
            uint32_t u0, u1;
            memcpy(&u0, &h0, 4); memcpy(&u1, &h1, 4);
            asm volatile("st.shared.v2.b32 [%0], {%1, %2};"
                :: "r"(base + ((af_row + r * 32) * BKP + af_col) * 2), "r"(u0), "r"(u1)
                : "memory");
        }
    };

    // prologue: stages 0 and 1
    cpB(0, 0);
    if (CONV) { ldgA(0); stsA(0); } else cpA(0, 0);
    cp_commit();
    cpB(1, 1);
    if (CONV) { ldgA(1); stsA(1); } else cpA(1, 1);
    cp_commit();

    for (int it = 0; it < NIT; it++) {
        int st = it % NSTG;
        if (it == NIT - 1) cp_wait0(); else cp_wait1();
        __syncthreads();
        bool pf = (it + 2 < NIT);
        if (pf) {
            int st2 = (it + 2) % NSTG;
            cpB(it + 2, st2);
            if (CONV) ldgA(it + 2);
            else cpA(it + 2, st2);
            cp_commit();
        }

        uint32_t a_base = sA(st), b_base = sB(st);
        #pragma unroll
        for (int ks = 0; ks < BK; ks += 16) {
            uint32_t bf[2][4];
            #pragma unroll
            for (int j2 = 0; j2 < 2; j2++)
                ldsm4t(bf[j2], b_base + ((ks + b_r) * BNP + wn + j2 * 16 + b_c) * 2);
            #pragma unroll
            for (int i = 0; i < 4; i++) {
                uint32_t a[4];
                ldsm4(a, a_base + ((wm + i * 16 + a_r) * BKP + ks + a_c) * 2);
                #pragma unroll
                for (int j = 0; j < 4; j++)
                    mma16816(acc[i][j], a, bf[j >> 1][(j & 1) * 2], bf[j >> 1][(j & 1) * 2 + 1]);
            }
        }
        if (pf && CONV) stsA((it + 2) % NSTG);
    }

    if (FUSE) __syncthreads();
    __half2* Ct = reinterpret_cast<__half2*>(sm);

    // --- store C (fp16), optionally also to smem tile for fused scan ---
    #pragma unroll
    for (int i = 0; i < 4; i++) {
        int rl0 = wm + i * 16 + (lane >> 2);
        int r0 = by * BM + rl0;
        int cl0 = wn + (lane & 3) * 2;
        int c0 = bx * BN + cl0;
        #pragma unroll
        for (int j = 0; j < 4; j++) {
            __half2 v0 = __floats2half2_rn(acc[i][j][0], acc[i][j][1]);
            __half2 v1 = __floats2half2_rn(acc[i][j][2], acc[i][j][3]);
            *reinterpret_cast<__half2*>(&C[(size_t)r0 * 512 + c0 + j * 8]) = v0;
            *reinterpret_cast<__half2*>(&C[(size_t)(r0 + 8) * 512 + c0 + j * 8]) = v1;
            if (FUSE) {
                Ct[rl0 * CT_STRIDE + ((cl0 + j * 8) >> 1)] = v0;
                Ct[(rl0 + 8) * CT_STRIDE + ((cl0 + j * 8) >> 1)] = v1;
            }
        }
    }

    if (FUSE) {
        __syncthreads();
        int seg = tid >> 6;
        int pl = tid & 63;
        int pg = bx * 64 + pl;
        float ar = g_lbar[pg], ai = g_lbar[PP + pg];
        float sr = 0.0f, si = 0.0f;
        int t0 = seg * 32;
        #pragma unroll 4
        for (int t = t0; t < t0 + 32; t++) {
            float2 v = __half22float2(Ct[t * CT_STRIDE + pl]);
            float nr = fmaf(ar, sr, fmaf(-ai, si, v.x));
            float ni = fmaf(ar, si, fmaf(ai, sr, v.y));
            sr = nr; si = ni;
        }
        s_part[seg][pl] = make_float2(sr, si);
        __syncthreads();
        if (tid < 64) {
            int pg2 = bx * 64 + tid;
            float a32r = g_a32[pg2], a32i = g_a32[PP + pg2];
            float2 c = s_part[0][tid];
            #pragma unroll
            for (int k = 1; k < 4; k++) {
                float2 pk = s_part[k][tid];
                float cr = a32r * c.x - a32i * c.y + pk.x;
                float ci = a32r * c.y + a32i * c.x + pk.y;
                c.x = cr; c.y = ci;
            }
            size_t o = ((size_t)by * PP + pg2) * 2;
            g_carry[o] = c.x;
            g_carry[o + 1] = c.y;
        }
    }
}

// ---------------------------------------------------------------------------
// Fast prefix: 16 blocks x 256 threads; batch-load ALL 32 carries (full MLP,
// no predication), combine serially in registers, store all 32 prefixes.
// ---------------------------------------------------------------------------
__global__ __launch_bounds__(256) void k_scan_prefix_fast() {
    int b = blockIdx.x;
    int p = threadIdx.x;
    const float2* cr2 = reinterpret_cast<const float2*>(g_carry);
    float2* pf2 = reinterpret_cast<float2*>(g_prefix);

    float2 cb[NCHUNK];
    #pragma unroll
    for (int i = 0; i < NCHUNK; i++)
        cb[i] = cr2[(size_t)(b * NCHUNK + i) * PP + p];

    float ar = g_aC[p], ai = g_aC[PP + p];
    float sr = 0.0f, si = 0.0f;
    #pragma unroll
    for (int i = 0; i < NCHUNK; i++) {
        pf2[(size_t)(b * NCHUNK + i) * PP + p] = make_float2(sr, si);
        float nr = fmaf(ar, sr, fmaf(-ai, si, cb[i].x));
        float ni = fmaf(ar, si, fmaf(ai, sr, cb[i].y));
        sr = nr; si = ni;
    }
}

// ---------------------------------------------------------------------------
// Scan apply (lean round-6 form): seeded from g_prefix, streams Bu -> xs
// ---------------------------------------------------------------------------
__global__ __launch_bounds__(256) void k_scan_apply() {
    int blk = blockIdx.x;
    int b = blk / NCHUNK;
    int j = blk % NCHUNK;
    int p = threadIdx.x;
    float ar = g_lbar[p], ai = g_lbar[PP + p];
    size_t po = ((size_t)blk * PP + p) * 2;
    float sr = g_prefix[po], si = g_prefix[po + 1];
    const __half2* bu = reinterpret_cast<const __half2*>(g_Bu);
    __half2* xs = reinterpret_cast<__half2*>(g_XS);
    size_t base = ((size_t)b * LL + (size_t)j * CH) * PP + p;
    #pragma unroll 4
    for (int t = 0; t < CH; t++) {
        float2 v = __half22float2(bu[base + (size_t)t * PP]);
        float nr = fmaf(ar, sr, fmaf(-ai, si, v.x));
        float ni = fmaf(ar, si, fmaf(ai, sr, v.y));
        sr = nr; si = ni;
        xs[base + (size_t)t * PP] = __floats2half2_rn(sr, si);
    }
}

// ---------------------------------------------------------------------------
// Epilogue: y = gelu_tanh(ys + x*D); z = x + y; LayerNorm over H
// ---------------------------------------------------------------------------
__global__ __launch_bounds__(256) void k_epilogue(const float* __restrict__ x,
                                                  const float* __restrict__ D,
                                                  const float* __restrict__ ln_scale,
                                                  const float* __restrict__ ln_bias,
                                                  float* __restrict__ out) {
    int row = blockIdx.x;
    int tid = threadIdx.x;
    const __half2* ysr = reinterpret_cast<const __half2*>(g_ysh + (size_t)row * HH);
    const float2* xr = reinterpret_cast<const float2*>(x + (size_t)row * HH);
    const float2* D2 = reinterpret_cast<const float2*>(D);
    float zv[2];
    float sum = 0.0f, sum2 = 0.0f;
    {
        float2 ys2 = __half22float2(ysr[tid]);
        float2 xv = xr[tid];
        float2 dv = D2[tid];
        float yy[2] = {ys2.x + xv.x * dv.x, ys2.y + xv.y * dv.y};
        float xsv[2] = {xv.x, xv.y};
        #pragma unroll
        for (int e = 0; e < 2; e++) {
            float y = yy[e];
            float y3 = y * y * y;
            float u = 0.7978845608028654f * (y + 0.044715f * y3);
            float g = 0.5f * y * (1.0f + tanhf(u));
            float z = xsv[e] + g;
            zv[e] = z;
            sum += z; sum2 += z * z;
        }
    }
    __shared__ float s1[8], s2[8], stats[2];
    #pragma unroll
    for (int off = 16; off > 0; off >>= 1) {
        sum  += __shfl_down_sync(0xFFFFFFFFu, sum, off);
        sum2 += __shfl_down_sync(0xFFFFFFFFu, sum2, off);
    }
    int lane = tid & 31, wid = tid >> 5;
    if (lane == 0) { s1[wid] = sum; s2[wid] = sum2; }
    __syncthreads();
    if (tid == 0) {
        float a = 0.0f, bsum = 0.0f;
        #pragma unroll
        for (int i = 0; i < 8; i++) { a += s1[i]; bsum += s2[i]; }
        float mean = a * (1.0f / HH);
        float var = bsum * (1.0f / HH) - mean * mean;
        stats[0] = mean;
        stats[1] = rsqrtf(var + LN_EPS);
    }
    __syncthreads();
    float mean = stats[0], rstd = stats[1];
    const float2* sc2 = reinterpret_cast<const float2*>(ln_scale);
    const float2* bi2 = reinterpret_cast<const float2*>(ln_bias);
    float2 sc = sc2[tid], bi = bi2[tid];
    float2 o;
    o.x = (zv[0] - mean) * rstd * sc.x + bi.x;
    o.y = (zv[1] - mean) * rstd * sc.y + bi.y;
    reinterpret_cast<float2*>(out + (size_t)row * HH)[tid] = o;
}

// ---------------------------------------------------------------------------
// Launch
// ---------------------------------------------------------------------------
extern "C" void kernel_launch(void* const* d_in, const int* in_sizes, int n_in,
                              void* d_out, int out_size) {
    const float* x             = (const float*)d_in[0];
    const float* log_lambda_re = (const float*)d_in[1];
    const float* lambda_im     = (const float*)d_in[2];
    const float* B_re          = (const float*)d_in[3];
    const float* B_im          = (const float*)d_in[4];
    const float* C_re          = (const float*)d_in[5];
    const float* C_im          = (const float*)d_in[6];
    const float* D             = (const float*)d_in[7];
    const float* log_step      = (const float*)d_in[8];
    const float* ln_scale      = (const float*)d_in[9];
    const float* ln_bias       = (const float*)d_in[10];
    float* out = (float*)d_out;

    k_setup_small<<<1, 256>>>(log_lambda_re, lambda_im, log_step);
    k_setup_W<<<(PP * HH + 255) / 256, 256>>>(B_re, B_im, C_re, C_im);

    __half *gBu, *gXS, *gYS, *gW1, *gW2;
    cudaGetSymbolAddress((void**)&gBu, g_Bu);
    cudaGetSymbolAddress((void**)&gXS, g_XS);
    cudaGetSymbolAddress((void**)&gYS, g_ysh);
    cudaGetSymbolAddress((void**)&gW1, g_W1);
    cudaGetSymbolAddress((void**)&gW2, g_W2);

    dim3 grid(HH / BN, MM / BM);   // (4, 512)

    // GEMM1: Bu = x @ W1 (fp32 A converted in-kernel) + fused chunk-carry
    k_gemm_f16<true, true><<<grid, 256>>>(x, nullptr, gW1, gBu);

    // scan: fast batched prefix, then lean apply
    k_scan_prefix_fast<<<BB, 256>>>();
    k_scan_apply<<<BB * NCHUNK, 256>>>();

    // GEMM2: ys = xs @ W2 (fp16 A via cp.async)
    k_gemm_f16<false, false><<<grid, 256>>>(nullptr, gXS, gW2, gYS);

    // epilogue
    k_epilogue<<<MM, 256>>>(x, D, ln_scale, ln_bias, out);
}

// round 10
// speedup vs baseline: 1.1461x; 1.0384x over previous
#include <cuda_runtime.h>
#include <cuda_fp16.h>
#include <math.h>
#include <stdint.h>
#include <string.h>

// ---------------------------------------------------------------------------
// Problem constants
// ---------------------------------------------------------------------------
#define BB 16
#define LL 4096
#define HH 512
#define PP 256
#define MM (BB * LL)          // 65536 rows
#define KK 512                // GEMM K
#define CH 128                // scan chunk length
#define NCHUNK (LL / CH)      // 32
#define LN_EPS 1e-6f

// GEMM tiling
#define BM 128
#define BN 128
#define BK 32
#define NIT (KK / BK)         // 16
#define BKP 40                // A smem k-stride (halves)
#define BNP 136               // B smem n-stride (halves)
// 3-stage smem layout
#define SA_BYTES 10240        // 128*40*2
#define SB_BYTES 8704         // 32*136*2
#define STG_BYTES (SA_BYTES + SB_BYTES)   // 18944
#define NSTG 3
#define SM_BYTES (NSTG * STG_BYTES)       // 56832 >= 33792 (C tile reuse)
#define CT_STRIDE 66          // half2 per row (132 halves)

// ---------------------------------------------------------------------------
// Scratch (static __device__)
// Interleaved complex: col 2p = re, col 2p+1 = im.
// ---------------------------------------------------------------------------
__device__ __half g_Bu[(size_t)MM * KK];
__device__ __half g_XS[(size_t)MM * KK];
__device__ __half g_ysh[(size_t)MM * HH];
__device__ __half g_W1[KK * HH];
__device__ __half g_W2[KK * HH];
__device__ float g_lbar[2 * PP];
__device__ float g_a32[2 * PP];    // lbar^32
__device__ float g_aC[2 * PP];     // lbar^128
__device__ float g_coef[2 * PP];
__device__ float g_carry[BB * NCHUNK * 2 * PP];
__device__ float g_prefix[BB * NCHUNK * 2 * PP];
__device__ int   g_cnt[MM / BM];   // per row-block tile counter (reset each launch)

// ---------------------------------------------------------------------------
// PTX helpers
// ---------------------------------------------------------------------------
__device__ __forceinline__ uint32_t s2u(const void* p) {
    return (uint32_t)__cvta_generic_to_shared(p);
}
__device__ __forceinline__ void ldsm4(uint32_t* r, uint32_t a) {
    asm volatile("ldmatrix.sync.aligned.m8n8.x4.shared.b16 {%0,%1,%2,%3},[%4];\n"
                 : "=r"(r[0]), "=r"(r[1]), "=r"(r[2]), "=r"(r[3]) : "r"(a));
}
__device__ __forceinline__ void ldsm4t(uint32_t* r, uint32_t a) {
    asm volatile("ldmatrix.sync.aligned.m8n8.x4.trans.shared.b16 {%0,%1,%2,%3},[%4];\n"
                 : "=r"(r[0]), "=r"(r[1]), "=r"(r[2]), "=r"(r[3]) : "r"(a));
}
__device__ __forceinline__ void mma16816(float* d, const uint32_t* a, uint32_t b0, uint32_t b1) {
    asm volatile("mma.sync.aligned.m16n8k16.row.col.f32.f16.f16.f32 "
                 "{%0,%1,%2,%3},{%4,%5,%6,%7},{%8,%9},{%0,%1,%2,%3};\n"
                 : "+f"(d[0]), "+f"(d[1]), "+f"(d[2]), "+f"(d[3])
                 : "r"(a[0]), "r"(a[1]), "r"(a[2]), "r"(a[3]), "r"(b0), "r"(b1));
}
__device__ __forceinline__ void cp16(uint32_t dst, const void* src) {
    asm volatile("cp.async.cg.shared.global [%0], [%1], 16;" :: "r"(dst), "l"(src));
}
__device__ __forceinline__ void cp_commit() {
    asm volatile("cp.async.commit_group;" ::: "memory");
}
__device__ __forceinline__ void cp_wait1() {
    asm volatile("cp.async.wait_group 1;" ::: "memory");
}
__device__ __forceinline__ void cp_wait0() {
    asm volatile("cp.async.wait_group 0;" ::: "memory");
}

// ---------------------------------------------------------------------------
// Setup: per-p scalars
// ---------------------------------------------------------------------------
__global__ void k_setup_small(const float* __restrict__ log_lambda_re,
                              const float* __restrict__ lambda_im,
                              const float* __restrict__ log_step) {
    int p = threadIdx.x;
    if (p >= PP) return;
    float lam_re = -expf(log_lambda_re[p]);
    float lam_im = lambda_im[p];
    float st = expf(log_step[p]);
    float ar = lam_re * st, ai = lam_im * st;
    float e = expf(ar);
    float lbr = e * cosf(ai);
    float lbi = e * sinf(ai);
    g_lbar[p] = lbr; g_lbar[PP + p] = lbi;
    float nr = lbr - 1.0f, ni = lbi;
    float d2 = lam_re * lam_re + lam_im * lam_im;
    g_coef[p]      = (nr * lam_re + ni * lam_im) / d2;
    g_coef[PP + p] = (ni * lam_re - nr * lam_im) / d2;
    float sr = lbr, si = lbi;
    #pragma unroll
    for (int i = 0; i < 5; i++) {          // ^32
        float r2 = sr * sr - si * si;
        float i2 = 2.0f * sr * si;
        sr = r2; si = i2;
    }
    g_a32[p] = sr; g_a32[PP + p] = si;
    #pragma unroll
    for (int i = 0; i < 2; i++) {          // ^128
        float r2 = sr * sr - si * si;
        float i2 = 2.0f * sr * si;
        sr = r2; si = i2;
    }
    g_aC[p] = sr; g_aC[PP + p] = si;
}

// ---------------------------------------------------------------------------
// Setup: folded weights [k][n], fp16, interleaved complex columns.
// Also resets the per-row-block tile counters (replay-safe).
// ---------------------------------------------------------------------------
__global__ void k_setup_W(const float* __restrict__ B_re, const float* __restrict__ B_im,
                          const float* __restrict__ C_re, const float* __restrict__ C_im) {
    int idx = blockIdx.x * blockDim.x + threadIdx.x;
    if (idx < MM / BM) g_cnt[idx] = 0;
    if (idx >= PP * HH) return;
    int p = idx / HH;
    int h = idx % HH;
    float cr = g_coef[p], ci = g_coef[PP + p];
    float br = B_re[p * HH + h], bi = B_im[p * HH + h];
    float w1r = cr * br - ci * bi;
    float w1i = cr * bi + ci * br;
    g_W1[h * KK + 2 * p]     = __float2half_rn(w1r);
    g_W1[h * KK + 2 * p + 1] = __float2half_rn(w1i);
    g_W2[(2 * p) * HH + h]     = __float2half_rn( 2.0f * C_re[h * PP + p]);
    g_W2[(2 * p + 1) * HH + h] = __float2half_rn(-2.0f * C_im[h * PP + p]);
}

// ---------------------------------------------------------------------------
// 3-stage pipelined fp16 GEMM, 2 CTAs/SM.
// CONV:  A fp32 via LDG->regs->deferred STS.  !CONV: A fp16 via cp.async.
// FUSE_C: after store, compute scan-chunk carry from the C tile (GEMM1).
// FUSE_E: last CTA of each row block runs gelu+residual+LayerNorm (GEMM2).
// ---------------------------------------------------------------------------
template <bool CONV, bool FUSE_C, bool FUSE_E>
__global__ __launch_bounds__(256, 2) void k_gemm_f16(
    const float* __restrict__ Af,
    const __half* __restrict__ Ah,
    const __half* __restrict__ W,
    __half* __restrict__ C,
    const float* __restrict__ Xf,
    const float* __restrict__ Dv,
    const float* __restrict__ ln_scale,
    const float* __restrict__ ln_bias,
    float* __restrict__ out)
{
    __shared__ __align__(16) char sm[SM_BYTES];
    __shared__ float2 s_part[4][64];
    __shared__ int s_go;

    uint32_t smb = s2u(sm);
    int tid = threadIdx.x;
    int bx = blockIdx.x, by = blockIdx.y;
    int lane = tid & 31, wid = tid >> 5;
    int wm = (wid & 1) * 64;
    int wn = (wid >> 1) * 32;

    int a_r = lane & 15;
    int a_c = (lane >> 4) * 8;
    int b_r = (lane & 7) + ((lane >> 3) & 1) * 8;
    int b_c = (lane >> 4) * 8;

    float acc[4][4][4];
    #pragma unroll
    for (int i = 0; i < 4; i++)
        #pragma unroll
        for (int j = 0; j < 4; j++)
            #pragma unroll
            for (int c = 0; c < 4; c++) acc[i][j][c] = 0.0f;

    int af_row = tid >> 3, af_col = (tid & 7) * 4;
    float4 areg[4];

    auto sA = [&](int st) { return smb + st * STG_BYTES; };
    auto sB = [&](int st) { return smb + st * STG_BYTES + SA_BYTES; };

    auto cpB = [&](int it, int st) {
        uint32_t base = sB(st);
        #pragma unroll
        for (int i = 0; i < 2; i++) {
            int cidx = tid + 256 * i;
            int row = cidx >> 4;
            int c16 = cidx & 15;
            cp16(base + row * 272 + c16 * 16,
                 W + (size_t)(it * BK + row) * 512 + bx * BN + c16 * 8);
        }
    };
    auto cpA = [&](int it, int st) {
        uint32_t base = sA(st);
        #pragma unroll
        for (int i = 0; i < 2; i++) {
            int cidx = tid + 256 * i;
            int row = cidx >> 2;
            int c16 = cidx & 3;
            cp16(base + row * 80 + c16 * 16,
                 Ah + (size_t)(by * BM + row) * 512 + it * BK + c16 * 8);
        }
    };
    auto ldgA = [&](int it) {
        #pragma unroll
        for (int r = 0; r < 4; r++)
            areg[r] = *reinterpret_cast<const float4*>(
                Af + (size_t)(by * BM + af_row + r * 32) * 512 + it * BK + af_col);
    };
    auto stsA = [&](int st) {
        uint32_t base = sA(st);
        #pragma unroll
        for (int r = 0; r < 4; r++) {
            float4 v = areg[r];
            __half2 h0 = __floats2half2_rn(v.x, v.y);
            __half2 h1 = __floats2half2_rn(v.z, v.w);
            uint32_t u0, u1;
            memcpy(&u0, &h0, 4); memcpy(&u1, &h1, 4);
            asm volatile("st.shared.v2.b32 [%0], {%1, %2};"
                :: "r"(base + ((af_row + r * 32) * BKP + af_col) * 2), "r"(u0), "r"(u1)
                : "memory");
        }
    };

    // prologue: stages 0 and 1
    cpB(0, 0);
    if (CONV) { ldgA(0); stsA(0); } else cpA(0, 0);
    cp_commit();
    cpB(1, 1);
    if (CONV) { ldgA(1); stsA(1); } else cpA(1, 1);
    cp_commit();

    for (int it = 0; it < NIT; it++) {
        int st = it % NSTG;
        if (it == NIT - 1) cp_wait0(); else cp_wait1();
        __syncthreads();
        bool pf = (it + 2 < NIT);
        if (pf) {
            int st2 = (it + 2) % NSTG;
            cpB(it + 2, st2);
            if (CONV) ldgA(it + 2);
            else cpA(it + 2, st2);
            cp_commit();
        }

        uint32_t a_base = sA(st), b_base = sB(st);
        #pragma unroll
        for (int ks = 0; ks < BK; ks += 16) {
            uint32_t bf[2][4];
            #pragma unroll
            for (int j2 = 0; j2 < 2; j2++)
                ldsm4t(bf[j2], b_base + ((ks + b_r) * BNP + wn + j2 * 16 + b_c) * 2);
            #pragma unroll
            for (int i = 0; i < 4; i++) {
                uint32_t a[4];
                ldsm4(a, a_base + ((wm + i * 16 + a_r) * BKP + ks + a_c) * 2);
                #pragma unroll
                for (int j = 0; j < 4; j++)
                    mma16816(acc[i][j], a, bf[j >> 1][(j & 1) * 2], bf[j >> 1][(j & 1) * 2 + 1]);
            }
        }
        if (pf && CONV) stsA((it + 2) % NSTG);
    }

    if (FUSE_C) __syncthreads();
    __half2* Ct = reinterpret_cast<__half2*>(sm);

    // --- store C (fp16), optionally also to smem tile for fused scan ---
    #pragma unroll
    for (int i = 0; i < 4; i++) {
        int rl0 = wm + i * 16 + (lane >> 2);
        int r0 = by * BM + rl0;
        int cl0 = wn + (lane & 3) * 2;
        int c0 = bx * BN + cl0;
        #pragma unroll
        for (int j = 0; j < 4; j++) {
            __half2 v0 = __floats2half2_rn(acc[i][j][0], acc[i][j][1]);
            __half2 v1 = __floats2half2_rn(acc[i][j][2], acc[i][j][3]);
            *reinterpret_cast<__half2*>(&C[(size_t)r0 * 512 + c0 + j * 8]) = v0;
            *reinterpret_cast<__half2*>(&C[(size_t)(r0 + 8) * 512 + c0 + j * 8]) = v1;
            if (FUSE_C) {
                Ct[rl0 * CT_STRIDE + ((cl0 + j * 8) >> 1)] = v0;
                Ct[(rl0 + 8) * CT_STRIDE + ((cl0 + j * 8) >> 1)] = v1;
            }
        }
    }

    if (FUSE_C) {
        __syncthreads();
        int seg = tid >> 6;
        int pl = tid & 63;
        int pg = bx * 64 + pl;
        float ar = g_lbar[pg], ai = g_lbar[PP + pg];
        float sr = 0.0f, si = 0.0f;
        int t0 = seg * 32;
        #pragma unroll 4
        for (int t = t0; t < t0 + 32; t++) {
            float2 v = __half22float2(Ct[t * CT_STRIDE + pl]);
            float nr = fmaf(ar, sr, fmaf(-ai, si, v.x));
            float ni = fmaf(ar, si, fmaf(ai, sr, v.y));
            sr = nr; si = ni;
        }
        s_part[seg][pl] = make_float2(sr, si);
        __syncthreads();
        if (tid < 64) {
            int pg2 = bx * 64 + tid;
            float a32r = g_a32[pg2], a32i = g_a32[PP + pg2];
            float2 c = s_part[0][tid];
            #pragma unroll
            for (int k = 1; k < 4; k++) {
                float2 pk = s_part[k][tid];
                float cr = a32r * c.x - a32i * c.y + pk.x;
                float ci = a32r * c.y + a32i * c.x + pk.y;
                c.x = cr; c.y = ci;
            }
            size_t o = ((size_t)by * PP + pg2) * 2;
            g_carry[o] = c.x;
            g_carry[o + 1] = c.y;
        }
    }

    if (FUSE_E) {
        // last CTA of this 128-row block runs the full epilogue (L2-hot ys)
        __threadfence();
        if (tid == 0) s_go = (atomicAdd(&g_cnt[by], 1) == 3) ? 1 : 0;
        __syncthreads();
        if (s_go) {
            for (int r = wid; r < BM; r += 8) {
                int row = by * BM + r;
                const __half* ysr = C + (size_t)row * 512;
                const float* xr = Xf + (size_t)row * 512;
                float zv[16];
                float sum = 0.0f, sum2 = 0.0f;
                #pragma unroll
                for (int q = 0; q < 16; q++) {
                    int cc = lane + 32 * q;
                    float ys = __half2float(ysr[cc]);
                    float xv = xr[cc];
                    float y = ys + xv * Dv[cc];
                    float y3 = y * y * y;
                    float u = 0.7978845608028654f * (y + 0.044715f * y3);
                    float g = 0.5f * y * (1.0f + tanhf(u));
                    float z = xv + g;
                    zv[q] = z;
                    sum += z; sum2 += z * z;
                }
                #pragma unroll
                for (int off = 16; off > 0; off >>= 1) {
                    sum  += __shfl_xor_sync(0xFFFFFFFFu, sum, off);
                    sum2 += __shfl_xor_sync(0xFFFFFFFFu, sum2, off);
                }
                float mean = sum * (1.0f / HH);
                float var = sum2 * (1.0f / HH) - mean * mean;
                float rstd = rsqrtf(var + LN_EPS);
                float* outr = out + (size_t)row * 512;
                #pragma unroll
                for (int q = 0; q < 16; q++) {
                    int cc = lane + 32 * q;
                    outr[cc] = (zv[q] - mean) * rstd * ln_scale[cc] + ln_bias[cc];
                }
            }
        }
    }
}

// ---------------------------------------------------------------------------
// Fast prefix: 16 blocks x 256 threads; batch-load ALL 32 carries (full MLP),
// combine serially in registers, store all 32 prefixes.
// ---------------------------------------------------------------------------
__global__ __launch_bounds__(256) void k_scan_prefix_fast() {
    int b = blockIdx.x;
    int p = threadIdx.x;
    const float2* cr2 = reinterpret_cast<const float2*>(g_carry);
    float2* pf2 = reinterpret_cast<float2*>(g_prefix);

    float2 cb[NCHUNK];
    #pragma unroll
    for (int i = 0; i < NCHUNK; i++)
        cb[i] = cr2[(size_t)(b * NCHUNK + i) * PP + p];

    float ar = g_aC[p], ai = g_aC[PP + p];
    float sr = 0.0f, si = 0.0f;
    #pragma unroll
    for (int i = 0; i < NCHUNK; i++) {
        pf2[(size_t)(b * NCHUNK + i) * PP + p] = make_float2(sr, si);
        float nr = fmaf(ar, sr, fmaf(-ai, si, cb[i].x));
        float ni = fmaf(ar, si, fmaf(ai, sr, cb[i].y));
        sr = nr; si = ni;
    }
}

// ---------------------------------------------------------------------------
// Scan apply: seeded from g_prefix, streams Bu -> xs
// ---------------------------------------------------------------------------
__global__ __launch_bounds__(256) void k_scan_apply() {
    int blk = blockIdx.x;
    int b = blk / NCHUNK;
    int j = blk % NCHUNK;
    int p = threadIdx.x;
    float ar = g_lbar[p], ai = g_lbar[PP + p];
    size_t po = ((size_t)blk * PP + p) * 2;
    float sr = g_prefix[po], si = g_prefix[po + 1];
    const __half2* bu = reinterpret_cast<const __half2*>(g_Bu);
    __half2* xs = reinterpret_cast<__half2*>(g_XS);
    size_t base = ((size_t)b * LL + (size_t)j * CH) * PP + p;
    #pragma unroll 4
    for (int t = 0; t < CH; t++) {
        float2 v = __half22float2(bu[base + (size_t)t * PP]);
        float nr = fmaf(ar, sr, fmaf(-ai, si, v.x));
        float ni = fmaf(ar, si, fmaf(ai, sr, v.y));
        sr = nr; si = ni;
        xs[base + (size_t)t * PP] = __floats2half2_rn(sr, si);
    }
}

// ---------------------------------------------------------------------------
// Launch
// ---------------------------------------------------------------------------
extern "C" void kernel_launch(void* const* d_in, const int* in_sizes, int n_in,
                              void* d_out, int out_size) {
    const float* x             = (const float*)d_in[0];
    const float* log_lambda_re = (const float*)d_in[1];
    const float* lambda_im     = (const float*)d_in[2];
    const float* B_re          = (const float*)d_in[3];
    const float* B_im          = (const float*)d_in[4];
    const float* C_re          = (const float*)d_in[5];
    const float* C_im          = (const float*)d_in[6];
    const float* D             = (const float*)d_in[7];
    const float* log_step      = (const float*)d_in[8];
    const float* ln_scale      = (const float*)d_in[9];
    const float* ln_bias       = (const float*)d_in[10];
    float* out = (float*)d_out;

    k_setup_small<<<1, 256>>>(log_lambda_re, lambda_im, log_step);
    k_setup_W<<<(PP * HH + 255) / 256, 256>>>(B_re, B_im, C_re, C_im);

    __half *gBu, *gXS, *gYS, *gW1, *gW2;
    cudaGetSymbolAddress((void**)&gBu, g_Bu);
    cudaGetSymbolAddress((void**)&gXS, g_XS);
    cudaGetSymbolAddress((void**)&gYS, g_ysh);
    cudaGetSymbolAddress((void**)&gW1, g_W1);
    cudaGetSymbolAddress((void**)&gW2, g_W2);

    dim3 grid(HH / BN, MM / BM);   // (4, 512)

    // GEMM1: Bu = x @ W1 (fp32 A converted in-kernel) + fused chunk-carry
    k_gemm_f16<true, true, false><<<grid, 256>>>(
        x, nullptr, gW1, gBu, nullptr, nullptr, nullptr, nullptr, nullptr);

    // scan: fast batched prefix, then lean apply
    k_scan_prefix_fast<<<BB, 256>>>();
    k_scan_apply<<<BB * NCHUNK, 256>>>();

    // GEMM2: ys = xs @ W2 (fp16 A via cp.async) + fused LN epilogue
    k_gemm_f16<false, false, true><<<grid, 256>>>(
        nullptr, gXS, gW2, gYS, x, D, ln_scale, ln_bias, out);
}

// round 12
// speedup vs baseline: 1.1488x; 1.0024x over previous
#include <cuda_runtime.h>
#include <cuda_fp16.h>
#include <math.h>
#include <stdint.h>
#include <string.h>

// ---------------------------------------------------------------------------
// Problem constants
// ---------------------------------------------------------------------------
#define BB 16
#define LL 4096
#define HH 512
#define PP 256
#define MM (BB * LL)          // 65536 rows
#define KK 512                // GEMM K
#define CH 128                // scan chunk length
#define NCHUNK (LL / CH)      // 32
#define LN_EPS 1e-6f

// GEMM tiling
#define BM 128
#define BN 128
#define BK 32
#define NIT (KK / BK)         // 16
#define BKP 40                // A smem k-stride (halves)
#define BNP 136               // B smem n-stride (halves)
// 4-stage smem layout
#define SA_BYTES 10240        // 128*40*2
#define SB_BYTES 8704         // 32*136*2
#define STG_BYTES (SA_BYTES + SB_BYTES)   // 18944
#define NSTG 4
#define SM_BYTES (NSTG * STG_BYTES)       // 75776 >= 33792 (C tile reuse)
#define CT_STRIDE 66          // half2 per row (132 halves)
#define NROWBLK (MM / BM)     // 512

// ---------------------------------------------------------------------------
// Scratch (static __device__)
// Interleaved complex: col 2p = re, col 2p+1 = im.
// ---------------------------------------------------------------------------
__device__ __half g_Bu[(size_t)MM * KK];
__device__ __half g_XS[(size_t)MM * KK];
__device__ __half g_ysh[(size_t)MM * HH];
__device__ __half g_W1[KK * HH];
__device__ __half g_W2[KK * HH];
__device__ float g_lbar[2 * PP];
__device__ float g_a32[2 * PP];    // lbar^32
__device__ float g_aC[2 * PP];     // lbar^128
__device__ float g_carry[BB * NCHUNK * 2 * PP];
__device__ float g_prefix[BB * NCHUNK * 2 * PP];
__device__ int   g_cnt[NROWBLK];   // per row-block tile counter (reset each launch)

// ---------------------------------------------------------------------------
// PTX helpers
// ---------------------------------------------------------------------------
__device__ __forceinline__ uint32_t s2u(const void* p) {
    return (uint32_t)__cvta_generic_to_shared(p);
}
__device__ __forceinline__ void ldsm4(uint32_t* r, uint32_t a) {
    asm volatile("ldmatrix.sync.aligned.m8n8.x4.shared.b16 {%0,%1,%2,%3},[%4];\n"
                 : "=r"(r[0]), "=r"(r[1]), "=r"(r[2]), "=r"(r[3]) : "r"(a));
}
__device__ __forceinline__ void ldsm4t(uint32_t* r, uint32_t a) {
    asm volatile("ldmatrix.sync.aligned.m8n8.x4.trans.shared.b16 {%0,%1,%2,%3},[%4];\n"
                 : "=r"(r[0]), "=r"(r[1]), "=r"(r[2]), "=r"(r[3]) : "r"(a));
}
__device__ __forceinline__ void mma16816(float* d, const uint32_t* a, uint32_t b0, uint32_t b1) {
    asm volatile("mma.sync.aligned.m16n8k16.row.col.f32.f16.f16.f32 "
                 "{%0,%1,%2,%3},{%4,%5,%6,%7},{%8,%9},{%0,%1,%2,%3};\n"
                 : "+f"(d[0]), "+f"(d[1]), "+f"(d[2]), "+f"(d[3])
                 : "r"(a[0]), "r"(a[1]), "r"(a[2]), "r"(a[3]), "r"(b0), "r"(b1));
}
__device__ __forceinline__ void cp16(uint32_t dst, const void* src) {
    asm volatile("cp.async.cg.shared.global [%0], [%1], 16;" :: "r"(dst), "l"(src));
}
__device__ __forceinline__ void cp_commit() {
    asm volatile("cp.async.commit_group;" ::: "memory");
}
__device__ __forceinline__ void cp_wait2() {
    asm volatile("cp.async.wait_group 2;" ::: "memory");
}
__device__ __forceinline__ void cp_wait1() {
    asm volatile("cp.async.wait_group 1;" ::: "memory");
}
__device__ __forceinline__ void cp_wait0() {
    asm volatile("cp.async.wait_group 0;" ::: "memory");
}

// ---------------------------------------------------------------------------
// Shared per-p math (used by both setup paths)
// ---------------------------------------------------------------------------
__device__ __forceinline__ void lambda_math(float llr, float lim, float lst,
                                            float& lbr, float& lbi,
                                            float& cr, float& ci) {
    float lam_re = -expf(llr);
    float lam_im = lim;
    float st = expf(lst);
    float ar = lam_re * st, ai = lam_im * st;
    float e = expf(ar);
    lbr = e * cosf(ai);
    lbi = e * sinf(ai);
    float nr = lbr - 1.0f, ni = lbi;
    float d2 = lam_re * lam_re + lam_im * lam_im;
    cr = (nr * lam_re + ni * lam_im) / d2;
    ci = (ni * lam_re - nr * lam_im) / d2;
}

// ---------------------------------------------------------------------------
// Merged setup: block 0 writes scalar tables AND resets ALL 512 counters;
// other blocks build W1/W2 (recomputing coef locally).
// ---------------------------------------------------------------------------
__global__ void k_setup_all(const float* __restrict__ log_lambda_re,
                            const float* __restrict__ lambda_im,
                            const float* __restrict__ log_step,
                            const float* __restrict__ B_re,
                            const float* __restrict__ B_im,
                            const float* __restrict__ C_re,
                            const float* __restrict__ C_im) {
    if (blockIdx.x == 0) {
        int p = threadIdx.x;
        // reset ALL NROWBLK=512 counters with 256 threads (2 each)
        g_cnt[p] = 0;
        g_cnt[p + 256] = 0;
        if (p < PP) {
            float lbr, lbi, cr, ci;
            lambda_math(log_lambda_re[p], lambda_im[p], log_step[p], lbr, lbi, cr, ci);
            g_lbar[p] = lbr; g_lbar[PP + p] = lbi;
            float sr = lbr, si = lbi;
            #pragma unroll
            for (int i = 0; i < 5; i++) {      // ^32
                float r2 = sr * sr - si * si;
                float i2 = 2.0f * sr * si;
                sr = r2; si = i2;
            }
            g_a32[p] = sr; g_a32[PP + p] = si;
            #pragma unroll
            for (int i = 0; i < 2; i++) {      // ^128
                float r2 = sr * sr - si * si;
                float i2 = 2.0f * sr * si;
                sr = r2; si = i2;
            }
            g_aC[p] = sr; g_aC[PP + p] = si;
        }
        return;
    }
    int idx = (blockIdx.x - 1) * blockDim.x + threadIdx.x;
    if (idx >= PP * HH) return;
    int p = idx / HH;
    int h = idx % HH;
    float lbr, lbi, cr, ci;
    lambda_math(log_lambda_re[p], lambda_im[p], log_step[p], lbr, lbi, cr, ci);
    float br = B_re[p * HH + h], bi = B_im[p * HH + h];
    float w1r = cr * br - ci * bi;
    float w1i = cr * bi + ci * br;
    g_W1[h * KK + 2 * p]     = __float2half_rn(w1r);
    g_W1[h * KK + 2 * p + 1] = __float2half_rn(w1i);
    g_W2[(2 * p) * HH + h]     = __float2half_rn( 2.0f * C_re[h * PP + p]);
    g_W2[(2 * p + 1) * HH + h] = __float2half_rn(-2.0f * C_im[h * PP + p]);
}

// ---------------------------------------------------------------------------
// 4-stage pipelined fp16 GEMM, 2 CTAs/SM.
// CONV:  A fp32 via LDG->regs->deferred STS.  !CONV: A fp16 via cp.async.
// FUSE_C: after store, compute scan-chunk carry from the C tile (GEMM1).
// FUSE_E: last CTA of each row block runs gelu+residual+LayerNorm (GEMM2).
// ---------------------------------------------------------------------------
template <bool CONV, bool FUSE_C, bool FUSE_E>
__global__ __launch_bounds__(256, 2) void k_gemm_f16(
    const float* __restrict__ Af,
    const __half* __restrict__ Ah,
    const __half* __restrict__ W,
    __half* __restrict__ C,
    const float* __restrict__ Xf,
    const float* __restrict__ Dv,
    const float* __restrict__ ln_scale,
    const float* __restrict__ ln_bias,
    float* __restrict__ out)
{
    __shared__ __align__(16) char sm[SM_BYTES];
    __shared__ float2 s_part[4][64];
    __shared__ int s_go;

    uint32_t smb = s2u(sm);
    int tid = threadIdx.x;
    int bx = blockIdx.x, by = blockIdx.y;
    int lane = tid & 31, wid = tid >> 5;
    int wm = (wid & 1) * 64;
    int wn = (wid >> 1) * 32;

    int a_r = lane & 15;
    int a_c = (lane >> 4) * 8;
    int b_r = (lane & 7) + ((lane >> 3) & 1) * 8;
    int b_c = (lane >> 4) * 8;

    float acc[4][4][4];
    #pragma unroll
    for (int i = 0; i < 4; i++)
        #pragma unroll
        for (int j = 0; j < 4; j++)
            #pragma unroll
            for (int c = 0; c < 4; c++) acc[i][j][c] = 0.0f;

    int af_row = tid >> 3, af_col = (tid & 7) * 4;
    float4 areg[4];

    auto sA = [&](int st) { return smb + st * STG_BYTES; };
    auto sB = [&](int st) { return smb + st * STG_BYTES + SA_BYTES; };

    auto cpB = [&](int it, int st) {
        uint32_t base = sB(st);
        #pragma unroll
        for (int i = 0; i < 2; i++) {
            int cidx = tid + 256 * i;
            int row = cidx >> 4;
            int c16 = cidx & 15;
            cp16(base + row * 272 + c16 * 16,
                 W + (size_t)(it * BK + row) * 512 + bx * BN + c16 * 8);
        }
    };
    auto cpA = [&](int it, int st) {
        uint32_t base = sA(st);
        #pragma unroll
        for (int i = 0; i < 2; i++) {
            int cidx = tid + 256 * i;
            int row = cidx >> 2;
            int c16 = cidx & 3;
            cp16(base + row * 80 + c16 * 16,
                 Ah + (size_t)(by * BM + row) * 512 + it * BK + c16 * 8);
        }
    };
    auto ldgA = [&](int it) {
        #pragma unroll
        for (int r = 0; r < 4; r++)
            areg[r] = *reinterpret_cast<const float4*>(
                Af + (size_t)(by * BM + af_row + r * 32) * 512 + it * BK + af_col);
    };
    auto stsA = [&](int st) {
        uint32_t base = sA(st);
        #pragma unroll
        for (int r = 0; r < 4; r++) {
            float4 v = areg[r];
            __half2 h0 = __floats2half2_rn(v.x, v.y);
            __half2 h1 = __floats2half2_rn(v.z, v.w);
            uint32_t u0, u1;
            memcpy(&u0, &h0, 4); memcpy(&u1, &h1, 4);
            asm volatile("st.shared.v2.b32 [%0], {%1, %2};"
                :: "r"(base + ((af_row + r * 32) * BKP + af_col) * 2), "r"(u0), "r"(u1)
                : "memory");
        }
    };

    // prologue: stages 0,1,2
    #pragma unroll
    for (int s = 0; s < 3; s++) {
        cpB(s, s);
        if (CONV) { ldgA(s); stsA(s); } else cpA(s, s);
        cp_commit();
    }

    for (int it = 0; it < NIT; it++) {
        int st = it & 3;
        if (it < NIT - 2) cp_wait2();
        else if (it == NIT - 2) cp_wait1();
        else cp_wait0();
        __syncthreads();
        bool pf = (it + 3 < NIT);
        if (pf) {
            int st2 = (it + 3) & 3;
            cpB(it + 3, st2);
            if (CONV) ldgA(it + 3);
            else cpA(it + 3, st2);
            cp_commit();
        }

        uint32_t a_base = sA(st), b_base = sB(st);
        #pragma unroll
        for (int ks = 0; ks < BK; ks += 16) {
            uint32_t bf[2][4];
            #pragma unroll
            for (int j2 = 0; j2 < 2; j2++)
                ldsm4t(bf[j2], b_base + ((ks + b_r) * BNP + wn + j2 * 16 + b_c) * 2);
            #pragma unroll
            for (int i = 0; i < 4; i++) {
                uint32_t a[4];
                ldsm4(a, a_base + ((wm + i * 16 + a_r) * BKP + ks + a_c) * 2);
                #pragma unroll
                for (int j = 0; j < 4; j++)
                    mma16816(acc[i][j], a, bf[j >> 1][(j & 1) * 2], bf[j >> 1][(j & 1) * 2 + 1]);
            }
        }
        if (pf && CONV) stsA((it + 3) & 3);
    }

    if (FUSE_C) __syncthreads();
    __half2* Ct = reinterpret_cast<__half2*>(sm);

    // --- store C (fp16), optionally also to smem tile for fused scan ---
    #pragma unroll
    for (int i = 0; i < 4; i++) {
        int rl0 = wm + i * 16 + (lane >> 2);
        int r0 = by * BM + rl0;
        int cl0 = wn + (lane & 3) * 2;
        int c0 = bx * BN + cl0;
        #pragma unroll
        for (int j = 0; j < 4; j++) {
            __half2 v0 = __floats2half2_rn(acc[i][j][0], acc[i][j][1]);
            __half2 v1 = __floats2half2_rn(acc[i][j][2], acc[i][j][3]);
            *reinterpret_cast<__half2*>(&C[(size_t)r0 * 512 + c0 + j * 8]) = v0;
            *reinterpret_cast<__half2*>(&C[(size_t)(r0 + 8) * 512 + c0 + j * 8]) = v1;
            if (FUSE_C) {
                Ct[rl0 * CT_STRIDE + ((cl0 + j * 8) >> 1)] = v0;
                Ct[(rl0 + 8) * CT_STRIDE + ((cl0 + j * 8) >> 1)] = v1;
            }
        }
    }

    if (FUSE_C) {
        __syncthreads();
        int seg = tid >> 6;
        int pl = tid & 63;
        int pg = bx * 64 + pl;
        float ar = g_lbar[pg], ai = g_lbar[PP + pg];
        float sr = 0.0f, si = 0.0f;
        int t0 = seg * 32;
        #pragma unroll 4
        for (int t = t0; t < t0 + 32; t++) {
            float2 v = __half22float2(Ct[t * CT_STRIDE + pl]);
            float nr = fmaf(ar, sr, fmaf(-ai, si, v.x));
            float ni = fmaf(ar, si, fmaf(ai, sr, v.y));
            sr = nr; si = ni;
        }
        s_part[seg][pl] = make_float2(sr, si);
        __syncthreads();
        if (tid < 64) {
            int pg2 = bx * 64 + tid;
            float a32r = g_a32[pg2], a32i = g_a32[PP + pg2];
            float2 c = s_part[0][tid];
            #pragma unroll
            for (int k = 1; k < 4; k++) {
                float2 pk = s_part[k][tid];
                float cr = a32r * c.x - a32i * c.y + pk.x;
                float ci = a32r * c.y + a32i * c.x + pk.y;
                c.x = cr; c.y = ci;
            }
            size_t o = ((size_t)by * PP + pg2) * 2;
            g_carry[o] = c.x;
            g_carry[o + 1] = c.y;
        }
    }

    if (FUSE_E) {
        // last CTA of this 128-row block runs the full epilogue (L2-hot ys)
        __threadfence();
        if (tid == 0) s_go = (atomicAdd(&g_cnt[by], 1) == 3) ? 1 : 0;
        __syncthreads();
        if (s_go) {
            for (int r = wid; r < BM; r += 8) {
                int row = by * BM + r;
                const __half* ysr = C + (size_t)row * 512;
                const float* xr = Xf + (size_t)row * 512;
                float zv[16];
                float sum = 0.0f, sum2 = 0.0f;
                #pragma unroll
                for (int q = 0; q < 16; q++) {
                    int cc = lane + 32 * q;
                    float ys = __half2float(ysr[cc]);
                    float xv = xr[cc];
                    float y = ys + xv * Dv[cc];
                    float y3 = y * y * y;
                    float u = 0.7978845608028654f * (y + 0.044715f * y3);
                    float g = 0.5f * y * (1.0f + tanhf(u));
                    float z = xv + g;
                    zv[q] = z;
                    sum += z; sum2 += z * z;
                }
                #pragma unroll
                for (int off = 16; off > 0; off >>= 1) {
                    sum  += __shfl_xor_sync(0xFFFFFFFFu, sum, off);
                    sum2 += __shfl_xor_sync(0xFFFFFFFFu, sum2, off);
                }
                float mean = sum * (1.0f / HH);
                float var = sum2 * (1.0f / HH) - mean * mean;
                float rstd = rsqrtf(var + LN_EPS);
                float* outr = out + (size_t)row * 512;
                #pragma unroll
                for (int q = 0; q < 16; q++) {
                    int cc = lane + 32 * q;
                    outr[cc] = (zv[q] - mean) * rstd * ln_scale[cc] + ln_bias[cc];
                }
            }
        }
    }
}

// ---------------------------------------------------------------------------
// Fast prefix: 16 blocks x 256 threads; batch-load ALL 32 carries (full MLP),
// combine serially in registers, store all 32 prefixes.
// ---------------------------------------------------------------------------
__global__ __launch_bounds__(256) void k_scan_prefix_fast() {
    int b = blockIdx.x;
    int p = threadIdx.x;
    const float2* cr2 = reinterpret_cast<const float2*>(g_carry);
    float2* pf2 = reinterpret_cast<float2*>(g_prefix);

    float2 cb[NCHUNK];
    #pragma unroll
    for (int i = 0; i < NCHUNK; i++)
        cb[i] = cr2[(size_t)(b * NCHUNK + i) * PP + p];

    float ar = g_aC[p], ai = g_aC[PP + p];
    float sr = 0.0f, si = 0.0f;
    #pragma unroll
    for (int i = 0; i < NCHUNK; i++) {
        pf2[(size_t)(b * NCHUNK + i) * PP + p] = make_float2(sr, si);
        float nr = fmaf(ar, sr, fmaf(-ai, si, cb[i].x));
        float ni = fmaf(ar, si, fmaf(ai, sr, cb[i].y));
        sr = nr; si = ni;
    }
}

// ---------------------------------------------------------------------------
// Scan apply: seeded from g_prefix, streams Bu -> xs
// ---------------------------------------------------------------------------
__global__ __launch_bounds__(256) void k_scan_apply() {
    int blk = blockIdx.x;
    int b = blk / NCHUNK;
    int j = blk % NCHUNK;
    int p = threadIdx.x;
    float ar = g_lbar[p], ai = g_lbar[PP + p];
    size_t po = ((size_t)blk * PP + p) * 2;
    float sr = g_prefix[po], si = g_prefix[po + 1];
    const __half2* bu = reinterpret_cast<const __half2*>(g_Bu);
    __half2* xs = reinterpret_cast<__half2*>(g_XS);
    size_t base = ((size_t)b * LL + (size_t)j * CH) * PP + p;
    #pragma unroll 4
    for (int t = 0; t < CH; t++) {
        float2 v = __half22float2(bu[base + (size_t)t * PP]);
        float nr = fmaf(ar, sr, fmaf(-ai, si, v.x));
        float ni = fmaf(ar, si, fmaf(ai, sr, v.y));
        sr = nr; si = ni;
        xs[base + (size_t)t * PP] = __floats2half2_rn(sr, si);
    }
}

// ---------------------------------------------------------------------------
// Launch
// ---------------------------------------------------------------------------
extern "C" void kernel_launch(void* const* d_in, const int* in_sizes, int n_in,
                              void* d_out, int out_size) {
    const float* x             = (const float*)d_in[0];
    const float* log_lambda_re = (const float*)d_in[1];
    const float* lambda_im     = (const float*)d_in[2];
    const float* B_re          = (const float*)d_in[3];
    const float* B_im          = (const float*)d_in[4];
    const float* C_re          = (const float*)d_in[5];
    const float* C_im          = (const float*)d_in[6];
    const float* D             = (const float*)d_in[7];
    const float* log_step      = (const float*)d_in[8];
    const float* ln_scale      = (const float*)d_in[9];
    const float* ln_bias       = (const float*)d_in[10];
    float* out = (float*)d_out;

    // merged setup: block 0 = scalars + full counter reset, blocks 1.. = weights
    k_setup_all<<<1 + (PP * HH + 255) / 256, 256>>>(
        log_lambda_re, lambda_im, log_step, B_re, B_im, C_re, C_im);

    __half *gBu, *gXS, *gYS, *gW1, *gW2;
    cudaGetSymbolAddress((void**)&gBu, g_Bu);
    cudaGetSymbolAddress((void**)&gXS, g_XS);
    cudaGetSymbolAddress((void**)&gYS, g_ysh);
    cudaGetSymbolAddress((void**)&gW1, g_W1);
    cudaGetSymbolAddress((void**)&gW2, g_W2);

    dim3 grid(HH / BN, MM / BM);   // (4, 512)

    // GEMM1: Bu = x @ W1 (fp32 A converted in-kernel) + fused chunk-carry
    k_gemm_f16<true, true, false><<<grid, 256>>>(
        x, nullptr, gW1, gBu, nullptr, nullptr, nullptr, nullptr, nullptr);

    // scan: fast batched prefix, then lean apply
    k_scan_prefix_fast<<<BB, 256>>>();
    k_scan_apply<<<BB * NCHUNK, 256>>>();

    // GEMM2: ys = xs @ W2 (fp16 A via cp.async) + fused LN epilogue
    k_gemm_f16<false, false, true><<<grid, 256>>>(
        nullptr, gXS, gW2, gYS, x, D, ln_scale, ln_bias, out);
}

// round 13
// speedup vs baseline: 1.2935x; 1.1259x over previous
#include <cuda_runtime.h>
#include <cuda_fp16.h>
#include <math.h>
#include <stdint.h>
#include <string.h>

// ---------------------------------------------------------------------------
// Problem constants
// ---------------------------------------------------------------------------
#define BB 16
#define LL 4096
#define HH 512
#define PP 256
#define MM (BB * LL)          // 65536 rows
#define KK 512                // GEMM K
#define CH 128                // scan chunk length
#define NCHUNK (LL / CH)      // 32
#define LN_EPS 1e-6f

// GEMM tiling
#define BM 128
#define BN 128
#define BK 32
#define NIT (KK / BK)         // 16
#define BKP 40                // A smem k-stride (halves)
#define BNP 136               // B smem n-stride (halves)
// 4-stage smem layout
#define SA_BYTES 10240        // 128*40*2
#define SB_BYTES 8704         // 32*136*2
#define STG_BYTES (SA_BYTES + SB_BYTES)   // 18944
#define NSTG 4
#define SM_BYTES (NSTG * STG_BYTES)       // 75776 >= 33792 (C tile reuse)
#define CT_STRIDE 66          // half2 per row (132 halves)
#define NROWBLK (MM / BM)     // 512

// ---------------------------------------------------------------------------
// Scratch (static __device__)
// Interleaved complex: col 2p = re, col 2p+1 = im.
// ---------------------------------------------------------------------------
__device__ __half g_Bu[(size_t)MM * KK];
__device__ __half g_XS[(size_t)MM * KK];
__device__ __half g_ysh[(size_t)MM * HH];
__device__ __half g_W1[KK * HH];
__device__ __half g_W2[KK * HH];
__device__ float g_lbar[2 * PP];
__device__ float g_a32[2 * PP];    // lbar^32
__device__ float g_aC[2 * PP];     // lbar^128
__device__ float g_carry[BB * NCHUNK * 2 * PP];
__device__ float g_prefix[BB * NCHUNK * 2 * PP];
__device__ int   g_cnt[NROWBLK];   // per row-block tile counter (reset each launch)

// ---------------------------------------------------------------------------
// PTX helpers
// ---------------------------------------------------------------------------
__device__ __forceinline__ uint32_t s2u(const void* p) {
    return (uint32_t)__cvta_generic_to_shared(p);
}
__device__ __forceinline__ void ldsm4(uint32_t* r, uint32_t a) {
    asm volatile("ldmatrix.sync.aligned.m8n8.x4.shared.b16 {%0,%1,%2,%3},[%4];\n"
                 : "=r"(r[0]), "=r"(r[1]), "=r"(r[2]), "=r"(r[3]) : "r"(a));
}
__device__ __forceinline__ void ldsm4t(uint32_t* r, uint32_t a) {
    asm volatile("ldmatrix.sync.aligned.m8n8.x4.trans.shared.b16 {%0,%1,%2,%3},[%4];\n"
                 : "=r"(r[0]), "=r"(r[1]), "=r"(r[2]), "=r"(r[3]) : "r"(a));
}
__device__ __forceinline__ void mma16816(float* d, const uint32_t* a, uint32_t b0, uint32_t b1) {
    asm volatile("mma.sync.aligned.m16n8k16.row.col.f32.f16.f16.f32 "
                 "{%0,%1,%2,%3},{%4,%5,%6,%7},{%8,%9},{%0,%1,%2,%3};\n"
                 : "+f"(d[0]), "+f"(d[1]), "+f"(d[2]), "+f"(d[3])
                 : "r"(a[0]), "r"(a[1]), "r"(a[2]), "r"(a[3]), "r"(b0), "r"(b1));
}
__device__ __forceinline__ void cp16(uint32_t dst, const void* src) {
    asm volatile("cp.async.cg.shared.global [%0], [%1], 16;" :: "r"(dst), "l"(src));
}
__device__ __forceinline__ void cp_commit() {
    asm volatile("cp.async.commit_group;" ::: "memory");
}
__device__ __forceinline__ void cp_wait2() {
    asm volatile("cp.async.wait_group 2;" ::: "memory");
}
__device__ __forceinline__ void cp_wait1() {
    asm volatile("cp.async.wait_group 1;" ::: "memory");
}
__device__ __forceinline__ void cp_wait0() {
    asm volatile("cp.async.wait_group 0;" ::: "memory");
}

// ---------------------------------------------------------------------------
// Shared per-p math (used by both setup paths)
// ---------------------------------------------------------------------------
__device__ __forceinline__ void lambda_math(float llr, float lim, float lst,
                                            float& lbr, float& lbi,
                                            float& cr, float& ci) {
    float lam_re = -expf(llr);
    float lam_im = lim;
    float st = expf(lst);
    float ar = lam_re * st, ai = lam_im * st;
    float e = expf(ar);
    lbr = e * cosf(ai);
    lbi = e * sinf(ai);
    float nr = lbr - 1.0f, ni = lbi;
    float d2 = lam_re * lam_re + lam_im * lam_im;
    cr = (nr * lam_re + ni * lam_im) / d2;
    ci = (ni * lam_re - nr * lam_im) / d2;
}

// ---------------------------------------------------------------------------
// Merged setup: block 0 writes scalar tables AND resets ALL 512 counters;
// other blocks build W1/W2 (recomputing coef locally).
// ---------------------------------------------------------------------------
__global__ void k_setup_all(const float* __restrict__ log_lambda_re,
                            const float* __restrict__ lambda_im,
                            const float* __restrict__ log_step,
                            const float* __restrict__ B_re,
                            const float* __restrict__ B_im,
                            const float* __restrict__ C_re,
                            const float* __restrict__ C_im) {
    if (blockIdx.x == 0) {
        int p = threadIdx.x;
        g_cnt[p] = 0;
        g_cnt[p + 256] = 0;
        if (p < PP) {
            float lbr, lbi, cr, ci;
            lambda_math(log_lambda_re[p], lambda_im[p], log_step[p], lbr, lbi, cr, ci);
            g_lbar[p] = lbr; g_lbar[PP + p] = lbi;
            float sr = lbr, si = lbi;
            #pragma unroll
            for (int i = 0; i < 5; i++) {      // ^32
                float r2 = sr * sr - si * si;
                float i2 = 2.0f * sr * si;
                sr = r2; si = i2;
            }
            g_a32[p] = sr; g_a32[PP + p] = si;
            #pragma unroll
            for (int i = 0; i < 2; i++) {      // ^128
                float r2 = sr * sr - si * si;
                float i2 = 2.0f * sr * si;
                sr = r2; si = i2;
            }
            g_aC[p] = sr; g_aC[PP + p] = si;
        }
        return;
    }
    int idx = (blockIdx.x - 1) * blockDim.x + threadIdx.x;
    if (idx >= PP * HH) return;
    int p = idx / HH;
    int h = idx % HH;
    float lbr, lbi, cr, ci;
    lambda_math(log_lambda_re[p], lambda_im[p], log_step[p], lbr, lbi, cr, ci);
    float br = B_re[p * HH + h], bi = B_im[p * HH + h];
    float w1r = cr * br - ci * bi;
    float w1i = cr * bi + ci * br;
    g_W1[h * KK + 2 * p]     = __float2half_rn(w1r);
    g_W1[h * KK + 2 * p + 1] = __float2half_rn(w1i);
    g_W2[(2 * p) * HH + h]     = __float2half_rn( 2.0f * C_re[h * PP + p]);
    g_W2[(2 * p + 1) * HH + h] = __float2half_rn(-2.0f * C_im[h * PP + p]);
}

// ---------------------------------------------------------------------------
// 4-stage pipelined fp16 GEMM, 2 CTAs/SM.
// CONV:  A fp32 via LDG->regs->deferred STS.  !CONV: A fp16 via cp.async.
// FUSE_C: after store, compute scan-chunk carry from the C tile (GEMM1).
// FUSE_E: last CTA of each row block runs gelu+residual+LayerNorm (GEMM2).
// ---------------------------------------------------------------------------
template <bool CONV, bool FUSE_C, bool FUSE_E>
__global__ __launch_bounds__(256, 2) void k_gemm_f16(
    const float* __restrict__ Af,
    const __half* __restrict__ Ah,
    const __half* __restrict__ W,
    __half* __restrict__ C,
    const float* __restrict__ Xf,
    const float* __restrict__ Dv,
    const float* __restrict__ ln_scale,
    const float* __restrict__ ln_bias,
    float* __restrict__ out)
{
    __shared__ __align__(16) char sm[SM_BYTES];
    __shared__ float2 s_part[4][64];
    __shared__ int s_go;

    uint32_t smb = s2u(sm);
    int tid = threadIdx.x;
    int bx = blockIdx.x, by = blockIdx.y;
    int lane = tid & 31, wid = tid >> 5;
    int wm = (wid & 1) * 64;
    int wn = (wid >> 1) * 32;

    int a_r = lane & 15;
    int a_c = (lane >> 4) * 8;
    int b_r = (lane & 7) + ((lane >> 3) & 1) * 8;
    int b_c = (lane >> 4) * 8;

    float acc[4][4][4];
    #pragma unroll
    for (int i = 0; i < 4; i++)
        #pragma unroll
        for (int j = 0; j < 4; j++)
            #pragma unroll
            for (int c = 0; c < 4; c++) acc[i][j][c] = 0.0f;

    int af_row = tid >> 3, af_col = (tid & 7) * 4;
    float4 areg[4];

    auto sA = [&](int st) { return smb + st * STG_BYTES; };
    auto sB = [&](int st) { return smb + st * STG_BYTES + SA_BYTES; };

    auto cpB = [&](int it, int st) {
        uint32_t base = sB(st);
        #pragma unroll
        for (int i = 0; i < 2; i++) {
            int cidx = tid + 256 * i;
            int row = cidx >> 4;
            int c16 = cidx & 15;
            cp16(base + row * 272 + c16 * 16,
                 W + (size_t)(it * BK + row) * 512 + bx * BN + c16 * 8);
        }
    };
    auto cpA = [&](int it, int st) {
        uint32_t base = sA(st);
        #pragma unroll
        for (int i = 0; i < 2; i++) {
            int cidx = tid + 256 * i;
            int row = cidx >> 2;
            int c16 = cidx & 3;
            cp16(base + row * 80 + c16 * 16,
                 Ah + (size_t)(by * BM + row) * 512 + it * BK + c16 * 8);
        }
    };
    auto ldgA = [&](int it) {
        #pragma unroll
        for (int r = 0; r < 4; r++)
            areg[r] = *reinterpret_cast<const float4*>(
                Af + (size_t)(by * BM + af_row + r * 32) * 512 + it * BK + af_col);
    };
    auto stsA = [&](int st) {
        uint32_t base = sA(st);
        #pragma unroll
        for (int r = 0; r < 4; r++) {
            float4 v = areg[r];
            __half2 h0 = __floats2half2_rn(v.x, v.y);
            __half2 h1 = __floats2half2_rn(v.z, v.w);
            uint32_t u0, u1;
            memcpy(&u0, &h0, 4); memcpy(&u1, &h1, 4);
            asm volatile("st.shared.v2.b32 [%0], {%1, %2};"
                :: "r"(base + ((af_row + r * 32) * BKP + af_col) * 2), "r"(u0), "r"(u1)
                : "memory");
        }
    };

    // prologue: stages 0,1,2
    #pragma unroll
    for (int s = 0; s < 3; s++) {
        cpB(s, s);
        if (CONV) { ldgA(s); stsA(s); } else cpA(s, s);
        cp_commit();
    }

    for (int it = 0; it < NIT; it++) {
        int st = it & 3;
        if (it < NIT - 2) cp_wait2();
        else if (it == NIT - 2) cp_wait1();
        else cp_wait0();
        __syncthreads();
        bool pf = (it + 3 < NIT);
        if (pf) {
            int st2 = (it + 3) & 3;
            cpB(it + 3, st2);
            if (CONV) ldgA(it + 3);
            else cpA(it + 3, st2);
            cp_commit();
        }

        uint32_t a_base = sA(st), b_base = sB(st);
        #pragma unroll
        for (int ks = 0; ks < BK; ks += 16) {
            uint32_t bf[2][4];
            #pragma unroll
            for (int j2 = 0; j2 < 2; j2++)
                ldsm4t(bf[j2], b_base + ((ks + b_r) * BNP + wn + j2 * 16 + b_c) * 2);
            #pragma unroll
            for (int i = 0; i < 4; i++) {
                uint32_t a[4];
                ldsm4(a, a_base + ((wm + i * 16 + a_r) * BKP + ks + a_c) * 2);
                #pragma unroll
                for (int j = 0; j < 4; j++)
                    mma16816(acc[i][j], a, bf[j >> 1][(j & 1) * 2], bf[j >> 1][(j & 1) * 2 + 1]);
            }
        }
        if (pf && CONV) stsA((it + 3) & 3);
    }

    if (FUSE_C) __syncthreads();
    __half2* Ct = reinterpret_cast<__half2*>(sm);

    // --- store C (fp16), optionally also to smem tile for fused scan ---
    #pragma unroll
    for (int i = 0; i < 4; i++) {
        int rl0 = wm + i * 16 + (lane >> 2);
        int r0 = by * BM + rl0;
        int cl0 = wn + (lane & 3) * 2;
        int c0 = bx * BN + cl0;
        #pragma unroll
        for (int j = 0; j < 4; j++) {
            __half2 v0 = __floats2half2_rn(acc[i][j][0], acc[i][j][1]);
            __half2 v1 = __floats2half2_rn(acc[i][j][2], acc[i][j][3]);
            *reinterpret_cast<__half2*>(&C[(size_t)r0 * 512 + c0 + j * 8]) = v0;
            *reinterpret_cast<__half2*>(&C[(size_t)(r0 + 8) * 512 + c0 + j * 8]) = v1;
            if (FUSE_C) {
                Ct[rl0 * CT_STRIDE + ((cl0 + j * 8) >> 1)] = v0;
                Ct[(rl0 + 8) * CT_STRIDE + ((cl0 + j * 8) >> 1)] = v1;
            }
        }
    }

    if (FUSE_C) {
        __syncthreads();
        int seg = tid >> 6;
        int pl = tid & 63;
        int pg = bx * 64 + pl;
        float ar = g_lbar[pg], ai = g_lbar[PP + pg];
        float sr = 0.0f, si = 0.0f;
        int t0 = seg * 32;
        #pragma unroll 4
        for (int t = t0; t < t0 + 32; t++) {
            float2 v = __half22float2(Ct[t * CT_STRIDE + pl]);
            float nr = fmaf(ar, sr, fmaf(-ai, si, v.x));
            float ni = fmaf(ar, si, fmaf(ai, sr, v.y));
            sr = nr; si = ni;
        }
        s_part[seg][pl] = make_float2(sr, si);
        __syncthreads();
        if (tid < 64) {
            int pg2 = bx * 64 + tid;
            float a32r = g_a32[pg2], a32i = g_a32[PP + pg2];
            float2 c = s_part[0][tid];
            #pragma unroll
            for (int k = 1; k < 4; k++) {
                float2 pk = s_part[k][tid];
                float cr = a32r * c.x - a32i * c.y + pk.x;
                float ci = a32r * c.y + a32i * c.x + pk.y;
                c.x = cr; c.y = ci;
            }
            size_t o = ((size_t)by * PP + pg2) * 2;
            g_carry[o] = c.x;
            g_carry[o + 1] = c.y;
        }
    }

    if (FUSE_E) {
        // last CTA of this 128-row block runs the full epilogue (L2-hot ys)
        __threadfence();
        if (tid == 0) s_go = (atomicAdd(&g_cnt[by], 1) == 3) ? 1 : 0;
        __syncthreads();
        if (s_go) {
            for (int r = wid; r < BM; r += 8) {
                int row = by * BM + r;
                const __half* ysr = C + (size_t)row * 512;
                const float* xr = Xf + (size_t)row * 512;
                float zv[16];
                float sum = 0.0f, sum2 = 0.0f;
                #pragma unroll
                for (int q = 0; q < 16; q++) {
                    int cc = lane + 32 * q;
                    float ys = __half2float(ysr[cc]);
                    float xv = xr[cc];
                    float y = ys + xv * Dv[cc];
                    float y3 = y * y * y;
                    float u = 0.7978845608028654f * (y + 0.044715f * y3);
                    float g = 0.5f * y * (1.0f + tanhf(u));
                    float z = xv + g;
                    zv[q] = z;
                    sum += z; sum2 += z * z;
                }
                #pragma unroll
                for (int off = 16; off > 0; off >>= 1) {
                    sum  += __shfl_xor_sync(0xFFFFFFFFu, sum, off);
                    sum2 += __shfl_xor_sync(0xFFFFFFFFu, sum2, off);
                }
                float mean = sum * (1.0f / HH);
                float var = sum2 * (1.0f / HH) - mean * mean;
                float rstd = rsqrtf(var + LN_EPS);
                float* outr = out + (size_t)row * 512;
                #pragma unroll
                for (int q = 0; q < 16; q++) {
                    int cc = lane + 32 * q;
                    outr[cc] = (zv[q] - mean) * rstd * ln_scale[cc] + ln_bias[cc];
                }
            }
        }
    }
}

// ---------------------------------------------------------------------------
// Fast prefix: 16 blocks x 256 threads; batch-load ALL 32 carries (full MLP),
// combine serially in registers, store all 32 prefixes.
// ---------------------------------------------------------------------------
__global__ __launch_bounds__(256) void k_scan_prefix_fast() {
    int b = blockIdx.x;
    int p = threadIdx.x;
    const float2* cr2 = reinterpret_cast<const float2*>(g_carry);
    float2* pf2 = reinterpret_cast<float2*>(g_prefix);

    float2 cb[NCHUNK];
    #pragma unroll
    for (int i = 0; i < NCHUNK; i++)
        cb[i] = cr2[(size_t)(b * NCHUNK + i) * PP + p];

    float ar = g_aC[p], ai = g_aC[PP + p];
    float sr = 0.0f, si = 0.0f;
    #pragma unroll
    for (int i = 0; i < NCHUNK; i++) {
        pf2[(size_t)(b * NCHUNK + i) * PP + p] = make_float2(sr, si);
        float nr = fmaf(ar, sr, fmaf(-ai, si, cb[i].x));
        float ni = fmaf(ar, si, fmaf(ai, sr, cb[i].y));
        sr = nr; si = ni;
    }
}

// ---------------------------------------------------------------------------
// Scan apply: seeded from g_prefix, streams Bu -> xs in batch-16 tiles
// (16 independent loads in flight per thread, then serial recurrence).
// ---------------------------------------------------------------------------
#define TBATCH 16
__global__ __launch_bounds__(256) void k_scan_apply() {
    int blk = blockIdx.x;
    int b = blk / NCHUNK;
    int j = blk % NCHUNK;
    int p = threadIdx.x;
    float ar = g_lbar[p], ai = g_lbar[PP + p];
    size_t po = ((size_t)blk * PP + p) * 2;
    float sr = g_prefix[po], si = g_prefix[po + 1];
    const __half2* bu = reinterpret_cast<const __half2*>(g_Bu);
    __half2* xs = reinterpret_cast<__half2*>(g_XS);
    size_t base = ((size_t)b * LL + (size_t)j * CH) * PP + p;

    for (int t0 = 0; t0 < CH; t0 += TBATCH) {
        float2 v[TBATCH];
        #pragma unroll
        for (int t = 0; t < TBATCH; t++)
            v[t] = __half22float2(bu[base + (size_t)(t0 + t) * PP]);
        #pragma unroll
        for (int t = 0; t < TBATCH; t++) {
            float nr = fmaf(ar, sr, fmaf(-ai, si, v[t].x));
            float ni = fmaf(ar, si, fmaf(ai, sr, v[t].y));
            sr = nr; si = ni;
            xs[base + (size_t)(t0 + t) * PP] = __floats2half2_rn(sr, si);
        }
    }
}

// ---------------------------------------------------------------------------
// Launch
// ---------------------------------------------------------------------------
extern "C" void kernel_launch(void* const* d_in, const int* in_sizes, int n_in,
                              void* d_out, int out_size) {
    const float* x             = (const float*)d_in[0];
    const float* log_lambda_re = (const float*)d_in[1];
    const float* lambda_im     = (const float*)d_in[2];
    const float* B_re          = (const float*)d_in[3];
    const float* B_im          = (const float*)d_in[4];
    const float* C_re          = (const float*)d_in[5];
    const float* C_im          = (const float*)d_in[6];
    const float* D             = (const float*)d_in[7];
    const float* log_step      = (const float*)d_in[8];
    const float* ln_scale      = (const float*)d_in[9];
    const float* ln_bias       = (const float*)d_in[10];
    float* out = (float*)d_out;

    // merged setup: block 0 = scalars + full counter reset, blocks 1.. = weights
    k_setup_all<<<1 + (PP * HH + 255) / 256, 256>>>(
        log_lambda_re, lambda_im, log_step, B_re, B_im, C_re, C_im);

    __half *gBu, *gXS, *gYS, *gW1, *gW2;
    cudaGetSymbolAddress((void**)&gBu, g_Bu);
    cudaGetSymbolAddress((void**)&gXS, g_XS);
    cudaGetSymbolAddress((void**)&gYS, g_ysh);
    cudaGetSymbolAddress((void**)&gW1, g_W1);
    cudaGetSymbolAddress((void**)&gW2, g_W2);

    dim3 grid(HH / BN, MM / BM);   // (4, 512)

    // GEMM1: Bu = x @ W1 (fp32 A converted in-kernel) + fused chunk-carry
    k_gemm_f16<true, true, false><<<grid, 256>>>(
        x, nullptr, gW1, gBu, nullptr, nullptr, nullptr, nullptr, nullptr);

    // scan: fast batched prefix, then batched-MLP apply
    k_scan_prefix_fast<<<BB, 256>>>();
    k_scan_apply<<<BB * NCHUNK, 256>>>();

    // GEMM2: ys = xs @ W2 (fp16 A via cp.async) + fused LN epilogue
    k_gemm_f16<false, false, true><<<grid, 256>>>(
        nullptr, gXS, gW2, gYS, x, D, ln_scale, ln_bias, out);
}